// round 1
// baseline (speedup 1.0000x reference)
#include <cuda_runtime.h>
#include <cuda_bf16.h>

// Problem constants
#define BB 32
#define TT 1024
#define DD 128
#define HH 4
#define DHH 32
#define MROWS (BB*TT)   // 32768

// Scratch (device globals — no allocation allowed)
__device__ float g_qkv[MROWS * 3 * DD];   // [32768, 384]
__device__ float g_attn[MROWS * DD];      // [32768, 128]
__device__ float g_proj[MROWS * DD];      // [32768, 128]

// ---------------------------------------------------------------------------
// Tiled fp32 GEMM: C[M,N] = A[M,128] * B[128,N].  BM=BN=64, BK=64, 256 thr,
// 4x4 register blocking. M,N multiples of 64. K fixed at 128.
// ---------------------------------------------------------------------------
__global__ __launch_bounds__(256) void gemm_k128(
    const float* __restrict__ A, const float* __restrict__ B,
    float* __restrict__ C, int N) {
    __shared__ float As[64][68];   // +4 pad: row stride 272B (16B aligned, bank-shifted)
    __shared__ float Bs[64][68];

    const int tid = threadIdx.x;
    const int tx = tid & 15;       // 0..15 -> output cols tx*4..tx*4+3
    const int ty = tid >> 4;       // 0..15 -> output rows ty*4..ty*4+3
    const int m0 = blockIdx.x * 64;
    const int n0 = blockIdx.y * 64;

    float acc[4][4];
#pragma unroll
    for (int r = 0; r < 4; r++)
#pragma unroll
        for (int c = 0; c < 4; c++) acc[r][c] = 0.f;

    for (int k0 = 0; k0 < 128; k0 += 64) {
        // Load A tile 64x64: 1024 float4, 4 per thread
#pragma unroll
        for (int r = 0; r < 4; r++) {
            int e = tid + r * 256;
            int row = e >> 4;       // 16 float4 per row
            int c4 = e & 15;
            float4 v = *(const float4*)&A[(size_t)(m0 + row) * 128 + k0 + c4 * 4];
            *(float4*)&As[row][c4 * 4] = v;
        }
        // Load B tile 64x64
#pragma unroll
        for (int r = 0; r < 4; r++) {
            int e = tid + r * 256;
            int row = e >> 4;
            int c4 = e & 15;
            float4 v = *(const float4*)&B[(size_t)(k0 + row) * N + n0 + c4 * 4];
            *(float4*)&Bs[row][c4 * 4] = v;
        }
        __syncthreads();
#pragma unroll
        for (int kk = 0; kk < 64; kk++) {
            float a0 = As[ty * 4 + 0][kk];
            float a1 = As[ty * 4 + 1][kk];
            float a2 = As[ty * 4 + 2][kk];
            float a3 = As[ty * 4 + 3][kk];
            float4 b = *(const float4*)&Bs[kk][tx * 4];
            acc[0][0] = fmaf(a0, b.x, acc[0][0]); acc[0][1] = fmaf(a0, b.y, acc[0][1]);
            acc[0][2] = fmaf(a0, b.z, acc[0][2]); acc[0][3] = fmaf(a0, b.w, acc[0][3]);
            acc[1][0] = fmaf(a1, b.x, acc[1][0]); acc[1][1] = fmaf(a1, b.y, acc[1][1]);
            acc[1][2] = fmaf(a1, b.z, acc[1][2]); acc[1][3] = fmaf(a1, b.w, acc[1][3]);
            acc[2][0] = fmaf(a2, b.x, acc[2][0]); acc[2][1] = fmaf(a2, b.y, acc[2][1]);
            acc[2][2] = fmaf(a2, b.z, acc[2][2]); acc[2][3] = fmaf(a2, b.w, acc[2][3]);
            acc[3][0] = fmaf(a3, b.x, acc[3][0]); acc[3][1] = fmaf(a3, b.y, acc[3][1]);
            acc[3][2] = fmaf(a3, b.z, acc[3][2]); acc[3][3] = fmaf(a3, b.w, acc[3][3]);
        }
        __syncthreads();
    }
#pragma unroll
    for (int r = 0; r < 4; r++) {
        float4 v = make_float4(acc[r][0], acc[r][1], acc[r][2], acc[r][3]);
        *(float4*)&C[(size_t)(m0 + ty * 4 + r) * N + n0 + tx * 4] = v;
    }
}

// ---------------------------------------------------------------------------
// Flash attention, fp32. One CTA = (q-block of 128, head h, batch b).
// One thread = one query row. K/V staged in 32-key smem tiles (broadcast reads).
// Causal + key-length mask; key loop bounded by min(q0+128, L_b).
// ---------------------------------------------------------------------------
__global__ __launch_bounds__(128) void attn_kernel(
    const float* __restrict__ qkv, const int* __restrict__ keys_length,
    float* __restrict__ out) {
    const int q0 = blockIdx.x * 128;
    const int h = blockIdx.y;
    const int b = blockIdx.z;
    const int tid = threadIdx.x;
    const int i = q0 + tid;                 // query index within sequence
    const float scale = 0.17677669529663687f;  // 1/sqrt(32)

    __shared__ float Ks[32][32];
    __shared__ float Vs[32][32];

    float q[32], o[32];
    {
        const float* qrow = qkv + ((size_t)(b * TT + i)) * 384 + h * 32;
#pragma unroll
        for (int c4 = 0; c4 < 8; c4++) {
            float4 v = *(const float4*)(qrow + c4 * 4);
            q[c4 * 4 + 0] = v.x * scale; q[c4 * 4 + 1] = v.y * scale;
            q[c4 * 4 + 2] = v.z * scale; q[c4 * 4 + 3] = v.w * scale;
        }
    }
#pragma unroll
    for (int d = 0; d < 32; d++) o[d] = 0.f;
    float m = -3.0e38f, l = 0.f;

    const int L = keys_length[b];
    const int kend = min(q0 + 128, L);      // >= 1 always (L >= 1)

    for (int j0 = 0; j0 < kend; j0 += 32) {
        const int jn = min(32, kend - j0);
        // Cooperative load of K,V tile: 256 float4 each, 2 per thread
#pragma unroll
        for (int r = 0; r < 2; r++) {
            int e = tid + r * 128;
            int row = e >> 3;     // 8 float4 per 32-float row
            int c4 = e & 7;
            float4 kk = make_float4(0.f, 0.f, 0.f, 0.f);
            float4 vv = kk;
            if (row < jn) {
                const float* base = qkv + ((size_t)(b * TT + j0 + row)) * 384 + h * 32;
                kk = *(const float4*)(base + 128 + c4 * 4);
                vv = *(const float4*)(base + 256 + c4 * 4);
            }
            *(float4*)&Ks[row][c4 * 4] = kk;
            *(float4*)&Vs[row][c4 * 4] = vv;
        }
        __syncthreads();

        if (j0 <= i) {   // this thread has at least one valid key in the tile
            float p[32];
            float mt = -3.0e38f;
#pragma unroll
            for (int j = 0; j < 32; j++) {
                float s = 0.f;
#pragma unroll
                for (int d = 0; d < 32; d++) s = fmaf(q[d], Ks[j][d], s);
                const int jg = j0 + j;
                bool valid = (jg <= i) && (j < jn);
                p[j] = valid ? s : -3.0e38f;
                mt = fmaxf(mt, p[j]);
            }
            const float mnew = fmaxf(m, mt);
            const float corr = __expf(m - mnew);
            float ps = 0.f;
#pragma unroll
            for (int j = 0; j < 32; j++) {
                p[j] = __expf(p[j] - mnew);   // masked -> exp(-huge) = 0
                ps += p[j];
            }
            l = l * corr + ps;
#pragma unroll
            for (int d = 0; d < 32; d++) {
                float acc = o[d] * corr;
#pragma unroll
                for (int j = 0; j < 32; j++) acc = fmaf(p[j], Vs[j][d], acc);
                o[d] = acc;
            }
            m = mnew;
        }
        __syncthreads();
    }

    const float inv = 1.f / l;
    float* orow = out + ((size_t)(b * TT + i)) * DD + h * 32;
#pragma unroll
    for (int c4 = 0; c4 < 8; c4++) {
        float4 v = make_float4(o[c4 * 4 + 0] * inv, o[c4 * 4 + 1] * inv,
                               o[c4 * 4 + 2] * inv, o[c4 * 4 + 3] * inv);
        *(float4*)(orow + c4 * 4) = v;
    }
}

// ---------------------------------------------------------------------------
// Residual + LayerNorm over D=128. One warp per row.
// ---------------------------------------------------------------------------
__global__ __launch_bounds__(256) void ln_kernel(
    const float* __restrict__ proj, const float* __restrict__ x,
    const float* __restrict__ gamma, const float* __restrict__ beta,
    float* __restrict__ out) {
    const int warp = threadIdx.x >> 5;
    const int lane = threadIdx.x & 31;
    const size_t row = (size_t)blockIdx.x * 8 + warp;
    const float* pr = proj + row * DD;
    const float* xr = x + row * DD;

    float v[4];
    float sum = 0.f, sq = 0.f;
#pragma unroll
    for (int r = 0; r < 4; r++) {
        int c = lane + r * 32;
        v[r] = pr[c] + xr[c];
        sum += v[r];
        sq = fmaf(v[r], v[r], sq);
    }
#pragma unroll
    for (int off = 16; off; off >>= 1) {
        sum += __shfl_xor_sync(0xffffffffu, sum, off);
        sq  += __shfl_xor_sync(0xffffffffu, sq, off);
    }
    const float mean = sum * (1.f / 128.f);
    const float var = sq * (1.f / 128.f) - mean * mean;
    const float rstd = rsqrtf(var + 1e-9f);

    float* orow = out + row * DD;
#pragma unroll
    for (int r = 0; r < 4; r++) {
        int c = lane + r * 32;
        orow[c] = (v[r] - mean) * rstd * gamma[c] + beta[c];
    }
}

// ---------------------------------------------------------------------------
extern "C" void kernel_launch(void* const* d_in, const int* in_sizes, int n_in,
                              void* d_out, int out_size) {
    const float* x           = (const float*)d_in[0];
    const int*   keys_length = (const int*)d_in[1];
    const float* W           = (const float*)d_in[2];
    const float* W_output    = (const float*)d_in[3];
    const float* gamma       = (const float*)d_in[4];
    const float* beta        = (const float*)d_in[5];
    float* out = (float*)d_out;

    float *qkv_p, *attn_p, *proj_p;
    cudaGetSymbolAddress((void**)&qkv_p,  g_qkv);
    cudaGetSymbolAddress((void**)&attn_p, g_attn);
    cudaGetSymbolAddress((void**)&proj_p, g_proj);

    // 1) QKV projection: [32768,128] @ [128,384]
    gemm_k128<<<dim3(MROWS / 64, 384 / 64), 256>>>(x, W, qkv_p, 384);

    // 2) Flash attention -> [32768,128] (heads concatenated)
    attn_kernel<<<dim3(TT / 128, HH, BB), 128>>>(qkv_p, keys_length, attn_p);

    // 3) Output projection: [32768,128] @ [128,128]
    gemm_k128<<<dim3(MROWS / 64, DD / 64), 256>>>(attn_p, W_output, proj_p, DD);

    // 4) Residual + LayerNorm
    ln_kernel<<<MROWS / 8, 256>>>(proj_p, x, gamma, beta, out);
}

// round 3
// speedup vs baseline: 1.1932x; 1.1932x over previous
#include <cuda_runtime.h>
#include <cuda_bf16.h>
#include <cstdint>

// Problem constants
#define BB 32
#define TT 1024
#define DD 128
#define HH 4
#define DHH 32
#define MROWS (BB*TT)   // 32768

// Scratch (device globals — no allocation allowed)
__device__ float g_qkv[MROWS * 3 * DD];   // [32768, 384]
__device__ float g_attn[MROWS * DD];      // [32768, 128]
__device__ float g_proj[MROWS * DD];      // [32768, 128]
__device__ uint32_t g_Ws[384 * 128];      // W^T split:  [n=384][k'=256 bf16 = 128 u32]
__device__ uint32_t g_WOs[128 * 128];     // Wout^T split

// ---------------------------------------------------------------------------
// helpers
// ---------------------------------------------------------------------------
__device__ __forceinline__ uint32_t smem_u32(const void* p) {
    uint32_t a;
    asm("{ .reg .u64 t; cvta.to.shared.u64 t, %1; cvt.u32.u64 %0, t; }"
        : "=r"(a) : "l"(p));
    return a;
}

// fp32 -> (hi bf16, lo bf16) packed u32; low 16 bits = hi (lower k' index)
__device__ __forceinline__ uint32_t split_pack(float x) {
    __nv_bfloat16 h = __float2bfloat16(x);
    float r = x - __bfloat162float(h);
    __nv_bfloat16 l = __float2bfloat16(r);
    return (uint32_t)__bfloat16_as_ushort(h) | ((uint32_t)__bfloat16_as_ushort(l) << 16);
}

#define LDSM_X4(r0, r1, r2, r3, addr) \
    asm volatile("ldmatrix.sync.aligned.m8n8.x4.shared.b16 {%0,%1,%2,%3}, [%4];" \
                 : "=r"(r0), "=r"(r1), "=r"(r2), "=r"(r3) : "r"(addr))

#define LDSM_X2(r0, r1, addr) \
    asm volatile("ldmatrix.sync.aligned.m8n8.x2.shared.b16 {%0,%1}, [%2];" \
                 : "=r"(r0), "=r"(r1) : "r"(addr))

#define MMA_16816(c, a, b) \
    asm volatile("mma.sync.aligned.m16n8k16.row.col.f32.bf16.bf16.f32 " \
                 "{%0,%1,%2,%3}, {%4,%5,%6,%7}, {%8,%9}, {%0,%1,%2,%3};" \
                 : "+f"((c)[0]), "+f"((c)[1]), "+f"((c)[2]), "+f"((c)[3]) \
                 : "r"((a)[0]), "r"((a)[1]), "r"((a)[2]), "r"((a)[3]), \
                   "r"((b)[0]), "r"((b)[1]))

// ---------------------------------------------------------------------------
// Prepass: transpose W / W_output and split fp32 -> (hi,lo) bf16 pairs.
// g_Ws[n][k] corresponds to W[k][n]. grid 512 x block 128.
// ---------------------------------------------------------------------------
__global__ void wsplit_kernel(const float* __restrict__ W,
                              const float* __restrict__ Wo,
                              uint32_t* __restrict__ Ws,
                              uint32_t* __restrict__ WOs) {
    int n = blockIdx.x;
    int k = threadIdx.x;   // 0..127
    if (n < 384) {
        Ws[n * 128 + k] = split_pack(W[k * 384 + n]);
    } else {
        int nn = n - 384;
        WOs[nn * 128 + k] = split_pack(Wo[k * 128 + nn]);
    }
}

// ---------------------------------------------------------------------------
// HMMA GEMM: C[M, Ntot] = A[M,128] * W[128,Ntot] via bf16 hi/lo split
// (K' = 256, chunked 4 x 64 bf16). CTA tile 128x128, 8 warps (2M x 4N),
// each warp 64x32 via m16n8k16. A split in-kernel; B pre-split [n][k'].
// ---------------------------------------------------------------------------
__global__ __launch_bounds__(256) void gemm_hmma(
    const float* __restrict__ A, const uint32_t* __restrict__ Bg,
    float* __restrict__ C, int Ntot) {
    // padded row stride 36 u32 (144B) -> conflict-free ldmatrix
    __shared__ uint32_t As_s[128 * 36];
    __shared__ uint32_t Bs_s[128 * 36];

    const int tid = threadIdx.x;
    const int wid = tid >> 5;
    const int lane = tid & 31;
    const int wm = wid >> 2;        // 0..1  -> rows wm*64
    const int wn = wid & 3;         // 0..3  -> cols wn*32
    const int m0 = blockIdx.x * 128;
    const int n0 = blockIdx.y * 128;

    const uint32_t sa = smem_u32(As_s);
    const uint32_t sb = smem_u32(Bs_s);

    float acc[4][4][4];
#pragma unroll
    for (int i = 0; i < 4; i++)
#pragma unroll
        for (int j = 0; j < 4; j++)
#pragma unroll
            for (int q = 0; q < 4; q++) acc[i][j][q] = 0.f;

    // precomputed ldmatrix lane addressing
    const int a_row = lane & 15;                // row within 16-row tile
    const int a_koff = (lane >> 4) * 4;         // u32 offset for k+8 blocks
    const int b_row = lane & 7;
    const int b_koff = ((lane >> 3) & 1) * 4;

    for (int ch = 0; ch < 4; ch++) {
        const int kc = ch * 32;   // fp32 k base of this chunk
        // A chunk: 128 rows x 32 fp32 -> split -> As_s[row][0..31]
#pragma unroll
        for (int r = 0; r < 4; r++) {
            int idx = tid + r * 256;          // 0..1023 float4 units
            int row = idx >> 3, c4 = idx & 7;
            float4 v = *(const float4*)&A[(size_t)(m0 + row) * 128 + kc + c4 * 4];
            uint32_t* d = &As_s[row * 36 + c4 * 4];
            d[0] = split_pack(v.x); d[1] = split_pack(v.y);
            d[2] = split_pack(v.z); d[3] = split_pack(v.w);
        }
        // B chunk: 128 n-rows x 32 u32 (pre-split)
#pragma unroll
        for (int r = 0; r < 4; r++) {
            int idx = tid + r * 256;
            int row = idx >> 3, c16 = idx & 7;
            uint4 v = *(const uint4*)&Bg[(size_t)(n0 + row) * 128 + kc + c16 * 4];
            uint32_t* d = &Bs_s[row * 36 + c16 * 4];
            d[0] = v.x; d[1] = v.y; d[2] = v.z; d[3] = v.w;
        }
        __syncthreads();

#pragma unroll
        for (int s = 0; s < 4; s++) {      // 4 k-steps of 16 bf16 = 8 u32
            uint32_t af[4][4];
#pragma unroll
            for (int tm = 0; tm < 4; tm++) {
                uint32_t addr = sa + (uint32_t)(((wm * 64 + tm * 16 + a_row) * 36 +
                                                 s * 8 + a_koff) * 4);
                LDSM_X4(af[tm][0], af[tm][1], af[tm][2], af[tm][3], addr);
            }
            uint32_t bf[4][2];
#pragma unroll
            for (int tn = 0; tn < 4; tn++) {
                uint32_t addr = sb + (uint32_t)(((wn * 32 + tn * 8 + b_row) * 36 +
                                                 s * 8 + b_koff) * 4);
                LDSM_X2(bf[tn][0], bf[tn][1], addr);
            }
#pragma unroll
            for (int tm = 0; tm < 4; tm++)
#pragma unroll
                for (int tn = 0; tn < 4; tn++)
                    MMA_16816(acc[tm][tn], af[tm], bf[tn]);
        }
        __syncthreads();
    }

    // Epilogue: lane l owns rows {g, g+8}, cols (l&3)*2 (+1)
    const int er = lane >> 2;
    const int ec = (lane & 3) * 2;
#pragma unroll
    for (int tm = 0; tm < 4; tm++) {
#pragma unroll
        for (int tn = 0; tn < 4; tn++) {
            int row = m0 + wm * 64 + tm * 16 + er;
            int col = n0 + wn * 32 + tn * 8 + ec;
            *(float2*)&C[(size_t)row * Ntot + col] =
                make_float2(acc[tm][tn][0], acc[tm][tn][1]);
            *(float2*)&C[(size_t)(row + 8) * Ntot + col] =
                make_float2(acc[tm][tn][2], acc[tm][tn][3]);
        }
    }
}

// ---------------------------------------------------------------------------
// Flash attention, fp32. One CTA = (q-block of 128, head h, batch b).
// ---------------------------------------------------------------------------
__global__ __launch_bounds__(128) void attn_kernel(
    const float* __restrict__ qkv, const int* __restrict__ keys_length,
    float* __restrict__ out) {
    const int q0 = blockIdx.x * 128;
    const int h = blockIdx.y;
    const int b = blockIdx.z;
    const int tid = threadIdx.x;
    const int i = q0 + tid;
    const float scale = 0.17677669529663687f;  // 1/sqrt(32)

    __shared__ float Ks[32][32];
    __shared__ float Vs[32][32];

    float q[32], o[32];
    {
        const float* qrow = qkv + ((size_t)(b * TT + i)) * 384 + h * 32;
#pragma unroll
        for (int c4 = 0; c4 < 8; c4++) {
            float4 v = *(const float4*)(qrow + c4 * 4);
            q[c4 * 4 + 0] = v.x * scale; q[c4 * 4 + 1] = v.y * scale;
            q[c4 * 4 + 2] = v.z * scale; q[c4 * 4 + 3] = v.w * scale;
        }
    }
#pragma unroll
    for (int d = 0; d < 32; d++) o[d] = 0.f;
    float m = -3.0e38f, l = 0.f;

    const int L = keys_length[b];
    const int kend = min(q0 + 128, L);

    for (int j0 = 0; j0 < kend; j0 += 32) {
        const int jn = min(32, kend - j0);
#pragma unroll
        for (int r = 0; r < 2; r++) {
            int e = tid + r * 128;
            int row = e >> 3;
            int c4 = e & 7;
            float4 kk = make_float4(0.f, 0.f, 0.f, 0.f);
            float4 vv = kk;
            if (row < jn) {
                const float* base = qkv + ((size_t)(b * TT + j0 + row)) * 384 + h * 32;
                kk = *(const float4*)(base + 128 + c4 * 4);
                vv = *(const float4*)(base + 256 + c4 * 4);
            }
            *(float4*)&Ks[row][c4 * 4] = kk;
            *(float4*)&Vs[row][c4 * 4] = vv;
        }
        __syncthreads();

        if (j0 <= i) {
            float p[32];
            float mt = -3.0e38f;
#pragma unroll
            for (int j = 0; j < 32; j++) {
                float s = 0.f;
#pragma unroll
                for (int d = 0; d < 32; d++) s = fmaf(q[d], Ks[j][d], s);
                const int jg = j0 + j;
                bool valid = (jg <= i) && (j < jn);
                p[j] = valid ? s : -3.0e38f;
                mt = fmaxf(mt, p[j]);
            }
            const float mnew = fmaxf(m, mt);
            const float corr = __expf(m - mnew);
            float ps = 0.f;
#pragma unroll
            for (int j = 0; j < 32; j++) {
                p[j] = __expf(p[j] - mnew);
                ps += p[j];
            }
            l = l * corr + ps;
#pragma unroll
            for (int d = 0; d < 32; d++) {
                float acc = o[d] * corr;
#pragma unroll
                for (int j = 0; j < 32; j++) acc = fmaf(p[j], Vs[j][d], acc);
                o[d] = acc;
            }
            m = mnew;
        }
        __syncthreads();
    }

    const float inv = 1.f / l;
    float* orow = out + ((size_t)(b * TT + i)) * DD + h * 32;
#pragma unroll
    for (int c4 = 0; c4 < 8; c4++) {
        float4 v = make_float4(o[c4 * 4 + 0] * inv, o[c4 * 4 + 1] * inv,
                               o[c4 * 4 + 2] * inv, o[c4 * 4 + 3] * inv);
        *(float4*)(orow + c4 * 4) = v;
    }
}

// ---------------------------------------------------------------------------
// Residual + LayerNorm over D=128. One warp per row.
// ---------------------------------------------------------------------------
__global__ __launch_bounds__(256) void ln_kernel(
    const float* __restrict__ proj, const float* __restrict__ x,
    const float* __restrict__ gamma, const float* __restrict__ beta,
    float* __restrict__ out) {
    const int warp = threadIdx.x >> 5;
    const int lane = threadIdx.x & 31;
    const size_t row = (size_t)blockIdx.x * 8 + warp;
    const float* pr = proj + row * DD;
    const float* xr = x + row * DD;

    float v[4];
    float sum = 0.f, sq = 0.f;
#pragma unroll
    for (int r = 0; r < 4; r++) {
        int c = lane + r * 32;
        v[r] = pr[c] + xr[c];
        sum += v[r];
        sq = fmaf(v[r], v[r], sq);
    }
#pragma unroll
    for (int off = 16; off; off >>= 1) {
        sum += __shfl_xor_sync(0xffffffffu, sum, off);
        sq  += __shfl_xor_sync(0xffffffffu, sq, off);
    }
    const float mean = sum * (1.f / 128.f);
    const float var = sq * (1.f / 128.f) - mean * mean;
    const float rstd = rsqrtf(var + 1e-9f);

    float* orow = out + row * DD;
#pragma unroll
    for (int r = 0; r < 4; r++) {
        int c = lane + r * 32;
        orow[c] = (v[r] - mean) * rstd * gamma[c] + beta[c];
    }
}

// ---------------------------------------------------------------------------
extern "C" void kernel_launch(void* const* d_in, const int* in_sizes, int n_in,
                              void* d_out, int out_size) {
    const float* x           = (const float*)d_in[0];
    const int*   keys_length = (const int*)d_in[1];
    const float* W           = (const float*)d_in[2];
    const float* W_output    = (const float*)d_in[3];
    const float* gamma       = (const float*)d_in[4];
    const float* beta        = (const float*)d_in[5];
    float* out = (float*)d_out;

    float *qkv_p, *attn_p, *proj_p;
    uint32_t *ws_p, *wos_p;
    cudaGetSymbolAddress((void**)&qkv_p,  g_qkv);
    cudaGetSymbolAddress((void**)&attn_p, g_attn);
    cudaGetSymbolAddress((void**)&proj_p, g_proj);
    cudaGetSymbolAddress((void**)&ws_p,   g_Ws);
    cudaGetSymbolAddress((void**)&wos_p,  g_WOs);

    // 0) Transpose + bf16 hi/lo split of both weight matrices
    wsplit_kernel<<<512, 128>>>(W, W_output, ws_p, wos_p);

    // 1) QKV projection: [32768,128] @ [128,384] (HMMA)
    gemm_hmma<<<dim3(MROWS / 128, 3), 256>>>(x, ws_p, qkv_p, 384);

    // 2) Flash attention -> [32768,128]
    attn_kernel<<<dim3(TT / 128, HH, BB), 128>>>(qkv_p, keys_length, attn_p);

    // 3) Output projection: [32768,128] @ [128,128] (HMMA)
    gemm_hmma<<<dim3(MROWS / 128, 1), 256>>>(attn_p, wos_p, proj_p, DD);

    // 4) Residual + LayerNorm
    ln_kernel<<<MROWS / 8, 256>>>(proj_p, x, gamma, beta, out);
}

// round 4
// speedup vs baseline: 2.0984x; 1.7587x over previous
#include <cuda_runtime.h>
#include <cuda_bf16.h>
#include <cstdint>

// Problem constants
#define BB 32
#define TT 1024
#define DD 128
#define HH 4
#define DHH 32
#define MROWS (BB*TT)   // 32768

// Scratch (device globals — no allocation allowed)
__device__ float g_qkv[MROWS * 3 * DD];   // [32768, 384]
__device__ float g_attn[MROWS * DD];      // [32768, 128]
__device__ float g_proj[MROWS * DD];      // [32768, 128]
__device__ uint32_t g_Ws[384 * 128];      // W^T split:  [n=384][k'=256 bf16 = 128 u32]
__device__ uint32_t g_WOs[128 * 128];     // Wout^T split

// ---------------------------------------------------------------------------
// helpers
// ---------------------------------------------------------------------------
__device__ __forceinline__ uint32_t smem_u32(const void* p) {
    uint32_t a;
    asm("{ .reg .u64 t; cvta.to.shared.u64 t, %1; cvt.u32.u64 %0, t; }"
        : "=r"(a) : "l"(p));
    return a;
}

// fp32 -> (hi bf16, lo bf16) packed u32; low 16 bits = hi (lower k' index)
__device__ __forceinline__ uint32_t split_pack(float x) {
    __nv_bfloat16 h = __float2bfloat16(x);
    float r = x - __bfloat162float(h);
    __nv_bfloat16 l = __float2bfloat16(r);
    return (uint32_t)__bfloat16_as_ushort(h) | ((uint32_t)__bfloat16_as_ushort(l) << 16);
}

// pack two floats as bf16x2: low 16 = x (even index), high 16 = y (odd index)
__device__ __forceinline__ uint32_t pack_bf16x2(float x, float y) {
    uint32_t d;
    asm("cvt.rn.bf16x2.f32 %0, %1, %2;" : "=r"(d) : "f"(y), "f"(x));
    return d;
}

__device__ __forceinline__ float ex2f(float x) {
    float r;
    asm("ex2.approx.ftz.f32 %0, %1;" : "=f"(r) : "f"(x));
    return r;
}

#define LDSM_X4(r0, r1, r2, r3, addr) \
    asm volatile("ldmatrix.sync.aligned.m8n8.x4.shared.b16 {%0,%1,%2,%3}, [%4];" \
                 : "=r"(r0), "=r"(r1), "=r"(r2), "=r"(r3) : "r"(addr))

#define LDSM_X2(r0, r1, addr) \
    asm volatile("ldmatrix.sync.aligned.m8n8.x2.shared.b16 {%0,%1}, [%2];" \
                 : "=r"(r0), "=r"(r1) : "r"(addr))

#define MMA_16816(c, a, b) \
    asm volatile("mma.sync.aligned.m16n8k16.row.col.f32.bf16.bf16.f32 " \
                 "{%0,%1,%2,%3}, {%4,%5,%6,%7}, {%8,%9}, {%0,%1,%2,%3};" \
                 : "+f"((c)[0]), "+f"((c)[1]), "+f"((c)[2]), "+f"((c)[3]) \
                 : "r"((a)[0]), "r"((a)[1]), "r"((a)[2]), "r"((a)[3]), \
                   "r"((b)[0]), "r"((b)[1]))

// ---------------------------------------------------------------------------
// Prepass: transpose W / W_output and split fp32 -> (hi,lo) bf16 pairs.
// ---------------------------------------------------------------------------
__global__ void wsplit_kernel(const float* __restrict__ W,
                              const float* __restrict__ Wo,
                              uint32_t* __restrict__ Ws,
                              uint32_t* __restrict__ WOs) {
    int n = blockIdx.x;
    int k = threadIdx.x;   // 0..127
    if (n < 384) {
        Ws[n * 128 + k] = split_pack(W[k * 384 + n]);
    } else {
        int nn = n - 384;
        WOs[nn * 128 + k] = split_pack(Wo[k * 128 + nn]);
    }
}

// ---------------------------------------------------------------------------
// HMMA GEMM: C[M, Ntot] = A[M,128] * W[128,Ntot] via bf16 hi/lo split.
// ---------------------------------------------------------------------------
__global__ __launch_bounds__(256) void gemm_hmma(
    const float* __restrict__ A, const uint32_t* __restrict__ Bg,
    float* __restrict__ C, int Ntot) {
    __shared__ uint32_t As_s[128 * 36];
    __shared__ uint32_t Bs_s[128 * 36];

    const int tid = threadIdx.x;
    const int wid = tid >> 5;
    const int lane = tid & 31;
    const int wm = wid >> 2;
    const int wn = wid & 3;
    const int m0 = blockIdx.x * 128;
    const int n0 = blockIdx.y * 128;

    const uint32_t sa = smem_u32(As_s);
    const uint32_t sb = smem_u32(Bs_s);

    float acc[4][4][4];
#pragma unroll
    for (int i = 0; i < 4; i++)
#pragma unroll
        for (int j = 0; j < 4; j++)
#pragma unroll
            for (int q = 0; q < 4; q++) acc[i][j][q] = 0.f;

    const int a_row = lane & 15;
    const int a_koff = (lane >> 4) * 4;
    const int b_row = lane & 7;
    const int b_koff = ((lane >> 3) & 1) * 4;

    for (int ch = 0; ch < 4; ch++) {
        const int kc = ch * 32;
#pragma unroll
        for (int r = 0; r < 4; r++) {
            int idx = tid + r * 256;
            int row = idx >> 3, c4 = idx & 7;
            float4 v = *(const float4*)&A[(size_t)(m0 + row) * 128 + kc + c4 * 4];
            uint32_t* d = &As_s[row * 36 + c4 * 4];
            d[0] = split_pack(v.x); d[1] = split_pack(v.y);
            d[2] = split_pack(v.z); d[3] = split_pack(v.w);
        }
#pragma unroll
        for (int r = 0; r < 4; r++) {
            int idx = tid + r * 256;
            int row = idx >> 3, c16 = idx & 7;
            uint4 v = *(const uint4*)&Bg[(size_t)(n0 + row) * 128 + kc + c16 * 4];
            uint32_t* d = &Bs_s[row * 36 + c16 * 4];
            d[0] = v.x; d[1] = v.y; d[2] = v.z; d[3] = v.w;
        }
        __syncthreads();

#pragma unroll
        for (int s = 0; s < 4; s++) {
            uint32_t af[4][4];
#pragma unroll
            for (int tm = 0; tm < 4; tm++) {
                uint32_t addr = sa + (uint32_t)(((wm * 64 + tm * 16 + a_row) * 36 +
                                                 s * 8 + a_koff) * 4);
                LDSM_X4(af[tm][0], af[tm][1], af[tm][2], af[tm][3], addr);
            }
            uint32_t bf[4][2];
#pragma unroll
            for (int tn = 0; tn < 4; tn++) {
                uint32_t addr = sb + (uint32_t)(((wn * 32 + tn * 8 + b_row) * 36 +
                                                 s * 8 + b_koff) * 4);
                LDSM_X2(bf[tn][0], bf[tn][1], addr);
            }
#pragma unroll
            for (int tm = 0; tm < 4; tm++)
#pragma unroll
                for (int tn = 0; tn < 4; tn++)
                    MMA_16816(acc[tm][tn], af[tm], bf[tn]);
        }
        __syncthreads();
    }

    const int er = lane >> 2;
    const int ec = (lane & 3) * 2;
#pragma unroll
    for (int tm = 0; tm < 4; tm++) {
#pragma unroll
        for (int tn = 0; tn < 4; tn++) {
            int row = m0 + wm * 64 + tm * 16 + er;
            int col = n0 + wn * 32 + tn * 8 + ec;
            *(float2*)&C[(size_t)row * Ntot + col] =
                make_float2(acc[tm][tn][0], acc[tm][tn][1]);
            *(float2*)&C[(size_t)(row + 8) * Ntot + col] =
                make_float2(acc[tm][tn][2], acc[tm][tn][3]);
        }
    }
}

// ---------------------------------------------------------------------------
// HMMA flash attention. CTA = (q-block 128, head, batch). 8 warps x 16 rows.
// Key tiles of 64. Scores/PV via bf16 3-term hi/lo split (cross terms kept).
// Softmax fp32 in exp2 domain (log2e folded into Q scale).
// ---------------------------------------------------------------------------
__global__ __launch_bounds__(256) void attn_hmma(
    const float* __restrict__ qkv, const int* __restrict__ keys_length,
    float* __restrict__ out) {
    // smem: Q split [128 rows][32 u32 payload], K split [64][32], Vt hi/lo [32][32]
    __shared__ uint32_t Qs[128 * 36];
    __shared__ uint32_t Ks[64 * 36];
    __shared__ uint32_t Vh[32 * 36];
    __shared__ uint32_t Vl[32 * 36];

    const int q0 = blockIdx.x * 128;
    const int h = blockIdx.y;
    const int b = blockIdx.z;
    const int tid = threadIdx.x;
    const int wid = tid >> 5;
    const int lane = tid & 31;

    const uint32_t sq = smem_u32(Qs);
    const uint32_t sk = smem_u32(Ks);
    const uint32_t svh = smem_u32(Vh);
    const uint32_t svl = smem_u32(Vl);

    const int L = keys_length[b];
    const int kend = min(q0 + 128, L);

    // ---- load + split Q (scale * log2e folded in) ----
    const float qscale = 0.17677669529663687f * 1.4426950408889634f;
    for (int idx = tid; idx < 128 * 16; idx += 256) {
        int row = idx >> 4, dp = idx & 15;
        const float* p = &qkv[((size_t)(b * TT + q0 + row)) * 384 + h * 32 + dp * 2];
        float x = p[0] * qscale, y = p[1] * qscale;
        uint32_t hi = pack_bf16x2(x, y);
        float hx = __uint_as_float(hi << 16);
        float hy = __uint_as_float(hi & 0xffff0000u);
        Qs[row * 36 + dp] = hi;
        Qs[row * 36 + 16 + dp] = pack_bf16x2(x - hx, y - hy);
    }

    float o[4][4];
#pragma unroll
    for (int nt = 0; nt < 4; nt++)
#pragma unroll
        for (int c = 0; c < 4; c++) o[nt][c] = 0.f;
    float m0 = -1e30f, m1 = -1e30f, l0 = 0.f, l1 = 0.f;

    const int r0 = q0 + wid * 16 + (lane >> 2);  // global row of c0,c1
    const int r1 = r0 + 8;                        // global row of c2,c3

    const int a_row = lane & 15;
    const int a_koff = (lane >> 4) * 4;
    const int b_row = lane & 7;
    const int b_koff = ((lane >> 3) & 1) * 4;

    __syncthreads();

    // ---- A fragments for Q (loaded once, reused every key tile) ----
    uint32_t aH[2][4], aL[2][4];
#pragma unroll
    for (int ks = 0; ks < 2; ks++) {
        uint32_t addr = sq + (uint32_t)(((wid * 16 + a_row) * 36 + ks * 8 + a_koff) * 4);
        LDSM_X4(aH[ks][0], aH[ks][1], aH[ks][2], aH[ks][3], addr);
        LDSM_X4(aL[ks][0], aL[ks][1], aL[ks][2], aL[ks][3], addr + 64);
    }

    for (int j0 = 0; j0 < kend; j0 += 64) {
        // ---- load + split K tile (64 keys) ----
        for (int idx = tid; idx < 64 * 16; idx += 256) {
            int row = idx >> 4, dp = idx & 15;
            int jj = min(j0 + row, TT - 1);
            const float* p = &qkv[((size_t)(b * TT + jj)) * 384 + 128 + h * 32 + dp * 2];
            float x = p[0], y = p[1];
            uint32_t hi = pack_bf16x2(x, y);
            float hx = __uint_as_float(hi << 16);
            float hy = __uint_as_float(hi & 0xffff0000u);
            Ks[row * 36 + dp] = hi;
            Ks[row * 36 + 16 + dp] = pack_bf16x2(x - hx, y - hy);
        }
        // ---- load + split + transpose V tile: Vt[d][j] ----
        for (int idx = tid; idx < 32 * 32; idx += 256) {
            int d = idx & 31, jp = idx >> 5;
            int ja = min(j0 + jp * 2, TT - 1);
            int jb = min(j0 + jp * 2 + 1, TT - 1);
            float v0 = qkv[((size_t)(b * TT + ja)) * 384 + 256 + h * 32 + d];
            float v1 = qkv[((size_t)(b * TT + jb)) * 384 + 256 + h * 32 + d];
            uint32_t hi = pack_bf16x2(v0, v1);
            float h0 = __uint_as_float(hi << 16);
            float h1 = __uint_as_float(hi & 0xffff0000u);
            Vh[d * 36 + jp] = hi;
            Vl[d * 36 + jp] = pack_bf16x2(v0 - h0, v1 - h1);
        }
        __syncthreads();

        // ---- scores S = Q K^T (3-term split) ----
        float s[8][4];
#pragma unroll
        for (int t = 0; t < 8; t++)
#pragma unroll
            for (int c = 0; c < 4; c++) s[t][c] = 0.f;

#pragma unroll
        for (int t = 0; t < 8; t++) {
            uint32_t krow = sk + (uint32_t)(((t * 8 + b_row) * 36 + b_koff) * 4);
            uint32_t bh0[2], bh1[2], bl0[2], bl1[2];
            LDSM_X2(bh0[0], bh0[1], krow);
            LDSM_X2(bh1[0], bh1[1], krow + 32);
            LDSM_X2(bl0[0], bl0[1], krow + 64);
            LDSM_X2(bl1[0], bl1[1], krow + 96);
            MMA_16816(s[t], aH[0], bh0);
            MMA_16816(s[t], aH[1], bh1);
            MMA_16816(s[t], aL[0], bh0);
            MMA_16816(s[t], aL[1], bh1);
            MMA_16816(s[t], aH[0], bl0);
            MMA_16816(s[t], aH[1], bl1);
        }

        // ---- masking (only boundary tiles) ----
        const bool needMask = (j0 + 64 > L) || (j0 + 64 > q0 + wid * 16 + 1);
        if (needMask) {
#pragma unroll
            for (int t = 0; t < 8; t++) {
#pragma unroll
                for (int c = 0; c < 2; c++) {
                    int j = j0 + t * 8 + (lane & 3) * 2 + c;
                    if (j > r0 || j >= L) s[t][c] = -1e30f;
                    if (j > r1 || j >= L) s[t][2 + c] = -1e30f;
                }
            }
        }

        // ---- online softmax (exp2 domain) ----
        float mt0 = -1e30f, mt1 = -1e30f;
#pragma unroll
        for (int t = 0; t < 8; t++) {
            mt0 = fmaxf(mt0, fmaxf(s[t][0], s[t][1]));
            mt1 = fmaxf(mt1, fmaxf(s[t][2], s[t][3]));
        }
        mt0 = fmaxf(mt0, __shfl_xor_sync(0xffffffffu, mt0, 1));
        mt0 = fmaxf(mt0, __shfl_xor_sync(0xffffffffu, mt0, 2));
        mt1 = fmaxf(mt1, __shfl_xor_sync(0xffffffffu, mt1, 1));
        mt1 = fmaxf(mt1, __shfl_xor_sync(0xffffffffu, mt1, 2));

        float mn0 = fmaxf(m0, mt0), mn1 = fmaxf(m1, mt1);
        float corr0 = ex2f(m0 - mn0), corr1 = ex2f(m1 - mn1);
        m0 = mn0; m1 = mn1;

        float ps0 = 0.f, ps1 = 0.f;
#pragma unroll
        for (int t = 0; t < 8; t++) {
            s[t][0] = ex2f(s[t][0] - mn0);
            s[t][1] = ex2f(s[t][1] - mn0);
            s[t][2] = ex2f(s[t][2] - mn1);
            s[t][3] = ex2f(s[t][3] - mn1);
            ps0 += s[t][0] + s[t][1];
            ps1 += s[t][2] + s[t][3];
        }
        ps0 += __shfl_xor_sync(0xffffffffu, ps0, 1);
        ps0 += __shfl_xor_sync(0xffffffffu, ps0, 2);
        ps1 += __shfl_xor_sync(0xffffffffu, ps1, 1);
        ps1 += __shfl_xor_sync(0xffffffffu, ps1, 2);
        l0 = l0 * corr0 + ps0;
        l1 = l1 * corr1 + ps1;

        // rescale O
#pragma unroll
        for (int nt = 0; nt < 4; nt++) {
            o[nt][0] *= corr0; o[nt][1] *= corr0;
            o[nt][2] *= corr1; o[nt][3] *= corr1;
        }

        // ---- pack P into A fragments (hi and lo) ----
        uint32_t ph[4][4], pl[4][4];
#pragma unroll
        for (int ks = 0; ks < 4; ks++) {
            const int t0 = 2 * ks, t1 = 2 * ks + 1;
            float v[8] = {s[t0][0], s[t0][1], s[t0][2], s[t0][3],
                          s[t1][0], s[t1][1], s[t1][2], s[t1][3]};
#pragma unroll
            for (int g = 0; g < 4; g++) {
                uint32_t hi = pack_bf16x2(v[g * 2], v[g * 2 + 1]);
                float h0 = __uint_as_float(hi << 16);
                float h1 = __uint_as_float(hi & 0xffff0000u);
                ph[ks][g] = hi;
                pl[ks][g] = pack_bf16x2(v[g * 2] - h0, v[g * 2 + 1] - h1);
            }
        }

        // ---- O += P V (3-term split) ----
#pragma unroll
        for (int nt = 0; nt < 4; nt++) {
            uint32_t vrow = (uint32_t)(((nt * 8 + b_row) * 36 + b_koff) * 4);
#pragma unroll
            for (int ks = 0; ks < 4; ks++) {
                uint32_t bvh[2], bvl[2];
                LDSM_X2(bvh[0], bvh[1], svh + vrow + (uint32_t)(ks * 32));
                LDSM_X2(bvl[0], bvl[1], svl + vrow + (uint32_t)(ks * 32));
                MMA_16816(o[nt], ph[ks], bvh);
                MMA_16816(o[nt], pl[ks], bvh);
                MMA_16816(o[nt], ph[ks], bvl);
            }
        }
        __syncthreads();
    }

    // ---- epilogue ----
    const float inv0 = 1.f / l0, inv1 = 1.f / l1;
#pragma unroll
    for (int nt = 0; nt < 4; nt++) {
        int d = h * 32 + nt * 8 + (lane & 3) * 2;
        *(float2*)&out[((size_t)(b * TT + r0)) * DD + d] =
            make_float2(o[nt][0] * inv0, o[nt][1] * inv0);
        *(float2*)&out[((size_t)(b * TT + r1)) * DD + d] =
            make_float2(o[nt][2] * inv1, o[nt][3] * inv1);
    }
}

// ---------------------------------------------------------------------------
// Residual + LayerNorm over D=128. One warp per row.
// ---------------------------------------------------------------------------
__global__ __launch_bounds__(256) void ln_kernel(
    const float* __restrict__ proj, const float* __restrict__ x,
    const float* __restrict__ gamma, const float* __restrict__ beta,
    float* __restrict__ out) {
    const int warp = threadIdx.x >> 5;
    const int lane = threadIdx.x & 31;
    const size_t row = (size_t)blockIdx.x * 8 + warp;
    const float* pr = proj + row * DD;
    const float* xr = x + row * DD;

    float v[4];
    float sum = 0.f, sq = 0.f;
#pragma unroll
    for (int r = 0; r < 4; r++) {
        int c = lane + r * 32;
        v[r] = pr[c] + xr[c];
        sum += v[r];
        sq = fmaf(v[r], v[r], sq);
    }
#pragma unroll
    for (int off = 16; off; off >>= 1) {
        sum += __shfl_xor_sync(0xffffffffu, sum, off);
        sq  += __shfl_xor_sync(0xffffffffu, sq, off);
    }
    const float mean = sum * (1.f / 128.f);
    const float var = sq * (1.f / 128.f) - mean * mean;
    const float rstd = rsqrtf(var + 1e-9f);

    float* orow = out + row * DD;
#pragma unroll
    for (int r = 0; r < 4; r++) {
        int c = lane + r * 32;
        orow[c] = (v[r] - mean) * rstd * gamma[c] + beta[c];
    }
}

// ---------------------------------------------------------------------------
extern "C" void kernel_launch(void* const* d_in, const int* in_sizes, int n_in,
                              void* d_out, int out_size) {
    const float* x           = (const float*)d_in[0];
    const int*   keys_length = (const int*)d_in[1];
    const float* W           = (const float*)d_in[2];
    const float* W_output    = (const float*)d_in[3];
    const float* gamma       = (const float*)d_in[4];
    const float* beta        = (const float*)d_in[5];
    float* out = (float*)d_out;

    float *qkv_p, *attn_p, *proj_p;
    uint32_t *ws_p, *wos_p;
    cudaGetSymbolAddress((void**)&qkv_p,  g_qkv);
    cudaGetSymbolAddress((void**)&attn_p, g_attn);
    cudaGetSymbolAddress((void**)&proj_p, g_proj);
    cudaGetSymbolAddress((void**)&ws_p,   g_Ws);
    cudaGetSymbolAddress((void**)&wos_p,  g_WOs);

    // 0) Transpose + bf16 hi/lo split of both weight matrices
    wsplit_kernel<<<512, 128>>>(W, W_output, ws_p, wos_p);

    // 1) QKV projection: [32768,128] @ [128,384] (HMMA)
    gemm_hmma<<<dim3(MROWS / 128, 3), 256>>>(x, ws_p, qkv_p, 384);

    // 2) Flash attention (HMMA) -> [32768,128]
    attn_hmma<<<dim3(TT / 128, HH, BB), 256>>>(qkv_p, keys_length, attn_p);

    // 3) Output projection: [32768,128] @ [128,128] (HMMA)
    gemm_hmma<<<dim3(MROWS / 128, 1), 256>>>(attn_p, wos_p, proj_p, DD);

    // 4) Residual + LayerNorm
    ln_kernel<<<MROWS / 8, 256>>>(proj_p, x, gamma, beta, out);
}

// round 5
// speedup vs baseline: 2.1438x; 1.0216x over previous
#include <cuda_runtime.h>
#include <cuda_bf16.h>
#include <cstdint>

// Problem constants
#define BB 32
#define TT 1024
#define DD 128
#define HH 4
#define DHH 32
#define MROWS (BB*TT)   // 32768

// Scratch (device globals — no allocation allowed)
__device__ __align__(16) float g_qkv[MROWS * 3 * DD];   // [32768, 384]
__device__ __align__(16) float g_attn[MROWS * DD];      // [32768, 128]
__device__ __align__(16) float g_proj[MROWS * DD];      // [32768, 128]
__device__ __align__(16) uint32_t g_Ws[384 * 128];      // W^T split
__device__ __align__(16) uint32_t g_WOs[128 * 128];     // Wout^T split
__device__ __align__(16) uint32_t g_Ksp[BB * HH * TT * 32];      // K split rows: 16 hi + 16 lo
__device__ __align__(16) uint32_t g_Vth[BB * HH * 32 * (TT/2)];  // V^T hi: [bh][d][jp]
__device__ __align__(16) uint32_t g_Vtl[BB * HH * 32 * (TT/2)];  // V^T lo

// ---------------------------------------------------------------------------
// helpers
// ---------------------------------------------------------------------------
__device__ __forceinline__ uint32_t smem_u32(const void* p) {
    uint32_t a;
    asm("{ .reg .u64 t; cvta.to.shared.u64 t, %1; cvt.u32.u64 %0, t; }"
        : "=r"(a) : "l"(p));
    return a;
}

__device__ __forceinline__ uint32_t split_pack(float x) {
    __nv_bfloat16 h = __float2bfloat16(x);
    float r = x - __bfloat162float(h);
    __nv_bfloat16 l = __float2bfloat16(r);
    return (uint32_t)__bfloat16_as_ushort(h) | ((uint32_t)__bfloat16_as_ushort(l) << 16);
}

// pack two floats as bf16x2: low 16 = x (even index), high 16 = y (odd index)
__device__ __forceinline__ uint32_t pack_bf16x2(float x, float y) {
    uint32_t d;
    asm("cvt.rn.bf16x2.f32 %0, %1, %2;" : "=r"(d) : "f"(y), "f"(x));
    return d;
}

__device__ __forceinline__ float ex2f(float x) {
    float r;
    asm("ex2.approx.ftz.f32 %0, %1;" : "=f"(r) : "f"(x));
    return r;
}

#define LDSM_X4(r0, r1, r2, r3, addr) \
    asm volatile("ldmatrix.sync.aligned.m8n8.x4.shared.b16 {%0,%1,%2,%3}, [%4];" \
                 : "=r"(r0), "=r"(r1), "=r"(r2), "=r"(r3) : "r"(addr))

#define LDSM_X2(r0, r1, addr) \
    asm volatile("ldmatrix.sync.aligned.m8n8.x2.shared.b16 {%0,%1}, [%2];" \
                 : "=r"(r0), "=r"(r1) : "r"(addr))

#define MMA_16816(c, a, b) \
    asm volatile("mma.sync.aligned.m16n8k16.row.col.f32.bf16.bf16.f32 " \
                 "{%0,%1,%2,%3}, {%4,%5,%6,%7}, {%8,%9}, {%0,%1,%2,%3};" \
                 : "+f"((c)[0]), "+f"((c)[1]), "+f"((c)[2]), "+f"((c)[3]) \
                 : "r"((a)[0]), "r"((a)[1]), "r"((a)[2]), "r"((a)[3]), \
                   "r"((b)[0]), "r"((b)[1]))

#define CP_ASYNC16(dst, src) \
    asm volatile("cp.async.cg.shared.global [%0], [%1], 16;" :: "r"(dst), "l"(src))
#define CP_COMMIT() asm volatile("cp.async.commit_group;" ::: "memory")
#define CP_WAIT(n)  asm volatile("cp.async.wait_group %0;" :: "n"(n) : "memory")

// ---------------------------------------------------------------------------
// Prepass 1: transpose W / W_output and split fp32 -> (hi,lo) bf16 pairs.
// ---------------------------------------------------------------------------
__global__ void wsplit_kernel(const float* __restrict__ W,
                              const float* __restrict__ Wo,
                              uint32_t* __restrict__ Ws,
                              uint32_t* __restrict__ WOs) {
    int n = blockIdx.x;
    int k = threadIdx.x;
    if (n < 384) {
        Ws[n * 128 + k] = split_pack(W[k * 384 + n]);
    } else {
        int nn = n - 384;
        WOs[nn * 128 + k] = split_pack(Wo[k * 128 + nn]);
    }
}

// ---------------------------------------------------------------------------
// Prepass 2: split K rows + split-transpose V, once globally. grid = 128 (bh).
// Ksp row j: u32[0..15] = hi bf16x2 (dims 2dp,2dp+1), u32[16..31] = lo.
// Vth/Vtl: [bh][d][jp] packing (v[2jp], v[2jp+1]).
// ---------------------------------------------------------------------------
__global__ __launch_bounds__(256) void kvsplit_kernel(
    const float* __restrict__ qkv, uint32_t* __restrict__ Ksp,
    uint32_t* __restrict__ Vth, uint32_t* __restrict__ Vtl) {
    const int bh = blockIdx.x;
    const int b = bh >> 2, h = bh & 3;
    const int tid = threadIdx.x;

    for (int idx = tid; idx < TT * 16; idx += 256) {
        int j = idx >> 4, dp = idx & 15;
        const float* p = &qkv[((size_t)(b * TT + j)) * 384 + 128 + h * 32 + dp * 2];
        float x = p[0], y = p[1];
        uint32_t hi = pack_bf16x2(x, y);
        float hx = __uint_as_float(hi << 16);
        float hy = __uint_as_float(hi & 0xffff0000u);
        uint32_t lo = pack_bf16x2(x - hx, y - hy);
        uint32_t* o = &Ksp[((size_t)(bh * TT + j)) * 32];
        o[dp] = hi; o[16 + dp] = lo;
    }
    for (int idx = tid; idx < 32 * (TT / 2); idx += 256) {
        int d = idx >> 9, jp = idx & 511;
        const float* base = &qkv[((size_t)(b * TT + jp * 2)) * 384 + 256 + h * 32 + d];
        float v0 = base[0], v1 = base[384];
        uint32_t hi = pack_bf16x2(v0, v1);
        float h0 = __uint_as_float(hi << 16);
        float h1 = __uint_as_float(hi & 0xffff0000u);
        uint32_t lo = pack_bf16x2(v0 - h0, v1 - h1);
        size_t o = (size_t)(bh * 32 + d) * (TT / 2) + jp;
        Vth[o] = hi; Vtl[o] = lo;
    }
}

// ---------------------------------------------------------------------------
// HMMA GEMM: C[M, Ntot] = A[M,128] * W[128,Ntot] via bf16 hi/lo split.
// ---------------------------------------------------------------------------
__global__ __launch_bounds__(256) void gemm_hmma(
    const float* __restrict__ A, const uint32_t* __restrict__ Bg,
    float* __restrict__ C, int Ntot) {
    __shared__ uint32_t As_s[128 * 36];
    __shared__ uint32_t Bs_s[128 * 36];

    const int tid = threadIdx.x;
    const int wid = tid >> 5;
    const int lane = tid & 31;
    const int wm = wid >> 2;
    const int wn = wid & 3;
    const int m0 = blockIdx.x * 128;
    const int n0 = blockIdx.y * 128;

    const uint32_t sa = smem_u32(As_s);
    const uint32_t sb = smem_u32(Bs_s);

    float acc[4][4][4];
#pragma unroll
    for (int i = 0; i < 4; i++)
#pragma unroll
        for (int j = 0; j < 4; j++)
#pragma unroll
            for (int q = 0; q < 4; q++) acc[i][j][q] = 0.f;

    const int a_row = lane & 15;
    const int a_koff = (lane >> 4) * 4;
    const int b_row = lane & 7;
    const int b_koff = ((lane >> 3) & 1) * 4;

    for (int ch = 0; ch < 4; ch++) {
        const int kc = ch * 32;
#pragma unroll
        for (int r = 0; r < 4; r++) {
            int idx = tid + r * 256;
            int row = idx >> 3, c4 = idx & 7;
            float4 v = *(const float4*)&A[(size_t)(m0 + row) * 128 + kc + c4 * 4];
            uint32_t* d = &As_s[row * 36 + c4 * 4];
            d[0] = split_pack(v.x); d[1] = split_pack(v.y);
            d[2] = split_pack(v.z); d[3] = split_pack(v.w);
        }
#pragma unroll
        for (int r = 0; r < 4; r++) {
            int idx = tid + r * 256;
            int row = idx >> 3, c16 = idx & 7;
            uint4 v = *(const uint4*)&Bg[(size_t)(n0 + row) * 128 + kc + c16 * 4];
            uint32_t* d = &Bs_s[row * 36 + c16 * 4];
            d[0] = v.x; d[1] = v.y; d[2] = v.z; d[3] = v.w;
        }
        __syncthreads();

#pragma unroll
        for (int s = 0; s < 4; s++) {
            uint32_t af[4][4];
#pragma unroll
            for (int tm = 0; tm < 4; tm++) {
                uint32_t addr = sa + (uint32_t)(((wm * 64 + tm * 16 + a_row) * 36 +
                                                 s * 8 + a_koff) * 4);
                LDSM_X4(af[tm][0], af[tm][1], af[tm][2], af[tm][3], addr);
            }
            uint32_t bf[4][2];
#pragma unroll
            for (int tn = 0; tn < 4; tn++) {
                uint32_t addr = sb + (uint32_t)(((wn * 32 + tn * 8 + b_row) * 36 +
                                                 s * 8 + b_koff) * 4);
                LDSM_X2(bf[tn][0], bf[tn][1], addr);
            }
#pragma unroll
            for (int tm = 0; tm < 4; tm++)
#pragma unroll
                for (int tn = 0; tn < 4; tn++)
                    MMA_16816(acc[tm][tn], af[tm], bf[tn]);
        }
        __syncthreads();
    }

    const int er = lane >> 2;
    const int ec = (lane & 3) * 2;
#pragma unroll
    for (int tm = 0; tm < 4; tm++) {
#pragma unroll
        for (int tn = 0; tn < 4; tn++) {
            int row = m0 + wm * 64 + tm * 16 + er;
            int col = n0 + wn * 32 + tn * 8 + ec;
            *(float2*)&C[(size_t)row * Ntot + col] =
                make_float2(acc[tm][tn][0], acc[tm][tn][1]);
            *(float2*)&C[(size_t)(row + 8) * Ntot + col] =
                make_float2(acc[tm][tn][2], acc[tm][tn][3]);
        }
    }
}

// ---------------------------------------------------------------------------
// HMMA flash attention with pre-split K/V, cp.async double-buffering, X4
// fragment loads, warp-level masked-tile skip.
// smem map (u32): buf0 [0,4608): K 64x36 | Vh 32x36 @2304 | Vl 32x36 @3456
//                 buf1 [4608,9216): same (Q staged here initially)
// ---------------------------------------------------------------------------
__global__ __launch_bounds__(256) void attn_hmma(
    const float* __restrict__ qkv, const int* __restrict__ keys_length,
    const uint32_t* __restrict__ Ksp, const uint32_t* __restrict__ Vth,
    const uint32_t* __restrict__ Vtl, float* __restrict__ out) {
    __shared__ __align__(16) uint32_t S[9216];

    const int q0 = blockIdx.x * 128;
    const int h = blockIdx.y;
    const int b = blockIdx.z;
    const int bh = b * HH + h;
    const int tid = threadIdx.x;
    const int wid = tid >> 5;
    const int lane = tid & 31;
    const uint32_t sS = smem_u32(S);

    const int L = keys_length[b];
    const int kend = min(q0 + 128, L);
    const int ntiles = (kend + 63) >> 6;

    const uint32_t* kbase = Ksp + (size_t)(bh * TT) * 32;
    const uint32_t* vhbase = Vth + (size_t)(bh * 32) * (TT / 2);
    const uint32_t* vlbase = Vtl + (size_t)(bh * 32) * (TT / 2);

    // ---- prefetch tile 0 into buf0 ----
    {
        const uint32_t sk = sS;
        const uint32_t* kt = kbase;
#pragma unroll
        for (int r = 0; r < 2; r++) {
            int idx = tid + r * 256;
            int row = idx >> 3, c4 = idx & 7;
            CP_ASYNC16(sk + (uint32_t)((row * 36 + c4 * 4) * 4), kt + row * 32 + c4 * 4);
        }
        {
            int d = tid >> 3, c4 = tid & 7;
            CP_ASYNC16(sk + (uint32_t)((2304 + d * 36 + c4 * 4) * 4),
                       vhbase + (size_t)d * (TT / 2) + c4 * 4);
            CP_ASYNC16(sk + (uint32_t)((3456 + d * 36 + c4 * 4) * 4),
                       vlbase + (size_t)d * (TT / 2) + c4 * 4);
        }
        CP_COMMIT();
    }

    // ---- stage Q split into buf1 region ----
    const float qscale = 0.17677669529663687f * 1.4426950408889634f;
    for (int idx = tid; idx < 128 * 16; idx += 256) {
        int row = idx >> 4, dp = idx & 15;
        const float* p = &qkv[((size_t)(b * TT + q0 + row)) * 384 + h * 32 + dp * 2];
        float x = p[0] * qscale, y = p[1] * qscale;
        uint32_t hi = pack_bf16x2(x, y);
        float hx = __uint_as_float(hi << 16);
        float hy = __uint_as_float(hi & 0xffff0000u);
        S[4608 + row * 36 + dp] = hi;
        S[4608 + row * 36 + 16 + dp] = pack_bf16x2(x - hx, y - hy);
    }
    __syncthreads();

    // ---- Q A-fragments (registers, reused every tile) ----
    const int a_row = lane & 15;
    const int a_koff = (lane >> 4) * 4;
    uint32_t aH[2][4], aL[2][4];
#pragma unroll
    for (int ks = 0; ks < 2; ks++) {
        uint32_t addr = sS + (uint32_t)((4608 + (wid * 16 + a_row) * 36 + ks * 8 + a_koff) * 4);
        LDSM_X4(aH[ks][0], aH[ks][1], aH[ks][2], aH[ks][3], addr);
        LDSM_X4(aL[ks][0], aL[ks][1], aL[ks][2], aL[ks][3], addr + 64);
    }
    __syncthreads();   // all Q fragments read; buf1 may be overwritten

    float o[4][4];
#pragma unroll
    for (int nt = 0; nt < 4; nt++)
#pragma unroll
        for (int c = 0; c < 4; c++) o[nt][c] = 0.f;
    float m0 = -1e30f, m1 = -1e30f, l0 = 0.f, l1 = 0.f;

    const int r0 = q0 + wid * 16 + (lane >> 2);
    const int r1 = r0 + 8;
    const int rmax = q0 + wid * 16 + 15;
    const int b_row = lane & 7;
    const int b_k4 = (lane >> 3) * 4;     // X4 column group: 0,4,8,12

    for (int t = 0; t < ntiles; t++) {
        if (t + 1 < ntiles) {
            // prefetch tile t+1 into buf (t+1)&1
            const uint32_t sk = sS + (uint32_t)(((t + 1) & 1) * 4608 * 4);
            const uint32_t* kt = kbase + (size_t)(t + 1) * 64 * 32;
#pragma unroll
            for (int r = 0; r < 2; r++) {
                int idx = tid + r * 256;
                int row = idx >> 3, c4 = idx & 7;
                CP_ASYNC16(sk + (uint32_t)((row * 36 + c4 * 4) * 4), kt + row * 32 + c4 * 4);
            }
            {
                int d = tid >> 3, c4 = tid & 7;
                CP_ASYNC16(sk + (uint32_t)((2304 + d * 36 + c4 * 4) * 4),
                           vhbase + (size_t)d * (TT / 2) + (t + 1) * 32 + c4 * 4);
                CP_ASYNC16(sk + (uint32_t)((3456 + d * 36 + c4 * 4) * 4),
                           vlbase + (size_t)d * (TT / 2) + (t + 1) * 32 + c4 * 4);
            }
            CP_COMMIT();
            CP_WAIT(1);   // tile t complete
        } else {
            CP_WAIT(0);
        }
        __syncthreads();

        const int j0 = t * 64;
        if (j0 <= rmax) {   // warp has at least one unmasked key in this tile
            const uint32_t skb = sS + (uint32_t)((t & 1) * 4608 * 4);

            // ---- scores S = Q K^T (3-term split) ----
            float s[8][4];
#pragma unroll
            for (int tt = 0; tt < 8; tt++)
#pragma unroll
                for (int c = 0; c < 4; c++) s[tt][c] = 0.f;

#pragma unroll
            for (int tt = 0; tt < 8; tt++) {
                uint32_t krow = skb + (uint32_t)(((tt * 8 + b_row) * 36 + b_k4) * 4);
                uint32_t bh0[2], bh1[2], bl0[2], bl1[2];
                LDSM_X4(bh0[0], bh0[1], bh1[0], bh1[1], krow);
                LDSM_X4(bl0[0], bl0[1], bl1[0], bl1[1], krow + 64);
                MMA_16816(s[tt], aH[0], bh0);
                MMA_16816(s[tt], aH[1], bh1);
                MMA_16816(s[tt], aL[0], bh0);
                MMA_16816(s[tt], aL[1], bh1);
                MMA_16816(s[tt], aH[0], bl0);
                MMA_16816(s[tt], aH[1], bl1);
            }

            // ---- masking (boundary tiles only) ----
            const bool needMask = (j0 + 64 > L) || (j0 + 64 > q0 + wid * 16 + 1);
            if (needMask) {
#pragma unroll
                for (int tt = 0; tt < 8; tt++) {
#pragma unroll
                    for (int c = 0; c < 2; c++) {
                        int j = j0 + tt * 8 + (lane & 3) * 2 + c;
                        if (j > r0 || j >= L) s[tt][c] = -1e30f;
                        if (j > r1 || j >= L) s[tt][2 + c] = -1e30f;
                    }
                }
            }

            // ---- online softmax (exp2 domain) ----
            float mt0 = -1e30f, mt1 = -1e30f;
#pragma unroll
            for (int tt = 0; tt < 8; tt++) {
                mt0 = fmaxf(mt0, fmaxf(s[tt][0], s[tt][1]));
                mt1 = fmaxf(mt1, fmaxf(s[tt][2], s[tt][3]));
            }
            mt0 = fmaxf(mt0, __shfl_xor_sync(0xffffffffu, mt0, 1));
            mt0 = fmaxf(mt0, __shfl_xor_sync(0xffffffffu, mt0, 2));
            mt1 = fmaxf(mt1, __shfl_xor_sync(0xffffffffu, mt1, 1));
            mt1 = fmaxf(mt1, __shfl_xor_sync(0xffffffffu, mt1, 2));

            float mn0 = fmaxf(m0, mt0), mn1 = fmaxf(m1, mt1);
            float corr0 = ex2f(m0 - mn0), corr1 = ex2f(m1 - mn1);
            m0 = mn0; m1 = mn1;

            float ps0 = 0.f, ps1 = 0.f;
#pragma unroll
            for (int tt = 0; tt < 8; tt++) {
                s[tt][0] = ex2f(s[tt][0] - mn0);
                s[tt][1] = ex2f(s[tt][1] - mn0);
                s[tt][2] = ex2f(s[tt][2] - mn1);
                s[tt][3] = ex2f(s[tt][3] - mn1);
                ps0 += s[tt][0] + s[tt][1];
                ps1 += s[tt][2] + s[tt][3];
            }
            ps0 += __shfl_xor_sync(0xffffffffu, ps0, 1);
            ps0 += __shfl_xor_sync(0xffffffffu, ps0, 2);
            ps1 += __shfl_xor_sync(0xffffffffu, ps1, 1);
            ps1 += __shfl_xor_sync(0xffffffffu, ps1, 2);
            l0 = l0 * corr0 + ps0;
            l1 = l1 * corr1 + ps1;

#pragma unroll
            for (int nt = 0; nt < 4; nt++) {
                o[nt][0] *= corr0; o[nt][1] *= corr0;
                o[nt][2] *= corr1; o[nt][3] *= corr1;
            }

            // ---- pack P into A fragments (hi and lo) ----
            uint32_t ph[4][4], pl[4][4];
#pragma unroll
            for (int ks = 0; ks < 4; ks++) {
                const int t0 = 2 * ks, t1 = 2 * ks + 1;
                float v[8] = {s[t0][0], s[t0][1], s[t0][2], s[t0][3],
                              s[t1][0], s[t1][1], s[t1][2], s[t1][3]};
#pragma unroll
                for (int g = 0; g < 4; g++) {
                    uint32_t hi = pack_bf16x2(v[g * 2], v[g * 2 + 1]);
                    float h0 = __uint_as_float(hi << 16);
                    float h1 = __uint_as_float(hi & 0xffff0000u);
                    ph[ks][g] = hi;
                    pl[ks][g] = pack_bf16x2(v[g * 2] - h0, v[g * 2 + 1] - h1);
                }
            }

            // ---- O += P V (3-term split) ----
            const uint32_t svhb = skb + 2304 * 4;
            const uint32_t svlb = skb + 3456 * 4;
#pragma unroll
            for (int nt = 0; nt < 4; nt++) {
                uint32_t voff = (uint32_t)(((nt * 8 + b_row) * 36 + b_k4) * 4);
                uint32_t bvh[4][2], bvl[4][2];
                LDSM_X4(bvh[0][0], bvh[0][1], bvh[1][0], bvh[1][1], svhb + voff);
                LDSM_X4(bvh[2][0], bvh[2][1], bvh[3][0], bvh[3][1], svhb + voff + 64);
                LDSM_X4(bvl[0][0], bvl[0][1], bvl[1][0], bvl[1][1], svlb + voff);
                LDSM_X4(bvl[2][0], bvl[2][1], bvl[3][0], bvl[3][1], svlb + voff + 64);
#pragma unroll
                for (int ks = 0; ks < 4; ks++) {
                    MMA_16816(o[nt], ph[ks], bvh[ks]);
                    MMA_16816(o[nt], pl[ks], bvh[ks]);
                    MMA_16816(o[nt], ph[ks], bvl[ks]);
                }
            }
        }
        __syncthreads();
    }

    // ---- epilogue ----
    const float inv0 = 1.f / l0, inv1 = 1.f / l1;
#pragma unroll
    for (int nt = 0; nt < 4; nt++) {
        int d = h * 32 + nt * 8 + (lane & 3) * 2;
        *(float2*)&out[((size_t)(b * TT + r0)) * DD + d] =
            make_float2(o[nt][0] * inv0, o[nt][1] * inv0);
        *(float2*)&out[((size_t)(b * TT + r1)) * DD + d] =
            make_float2(o[nt][2] * inv1, o[nt][3] * inv1);
    }
}

// ---------------------------------------------------------------------------
// Residual + LayerNorm over D=128. One warp per row.
// ---------------------------------------------------------------------------
__global__ __launch_bounds__(256) void ln_kernel(
    const float* __restrict__ proj, const float* __restrict__ x,
    const float* __restrict__ gamma, const float* __restrict__ beta,
    float* __restrict__ out) {
    const int warp = threadIdx.x >> 5;
    const int lane = threadIdx.x & 31;
    const size_t row = (size_t)blockIdx.x * 8 + warp;
    const float* pr = proj + row * DD;
    const float* xr = x + row * DD;

    float v[4];
    float sum = 0.f, sq = 0.f;
#pragma unroll
    for (int r = 0; r < 4; r++) {
        int c = lane + r * 32;
        v[r] = pr[c] + xr[c];
        sum += v[r];
        sq = fmaf(v[r], v[r], sq);
    }
#pragma unroll
    for (int off = 16; off; off >>= 1) {
        sum += __shfl_xor_sync(0xffffffffu, sum, off);
        sq  += __shfl_xor_sync(0xffffffffu, sq, off);
    }
    const float mean = sum * (1.f / 128.f);
    const float var = sq * (1.f / 128.f) - mean * mean;
    const float rstd = rsqrtf(var + 1e-9f);

    float* orow = out + row * DD;
#pragma unroll
    for (int r = 0; r < 4; r++) {
        int c = lane + r * 32;
        orow[c] = (v[r] - mean) * rstd * gamma[c] + beta[c];
    }
}

// ---------------------------------------------------------------------------
extern "C" void kernel_launch(void* const* d_in, const int* in_sizes, int n_in,
                              void* d_out, int out_size) {
    const float* x           = (const float*)d_in[0];
    const int*   keys_length = (const int*)d_in[1];
    const float* W           = (const float*)d_in[2];
    const float* W_output    = (const float*)d_in[3];
    const float* gamma       = (const float*)d_in[4];
    const float* beta        = (const float*)d_in[5];
    float* out = (float*)d_out;

    float *qkv_p, *attn_p, *proj_p;
    uint32_t *ws_p, *wos_p, *ksp_p, *vth_p, *vtl_p;
    cudaGetSymbolAddress((void**)&qkv_p,  g_qkv);
    cudaGetSymbolAddress((void**)&attn_p, g_attn);
    cudaGetSymbolAddress((void**)&proj_p, g_proj);
    cudaGetSymbolAddress((void**)&ws_p,   g_Ws);
    cudaGetSymbolAddress((void**)&wos_p,  g_WOs);
    cudaGetSymbolAddress((void**)&ksp_p,  g_Ksp);
    cudaGetSymbolAddress((void**)&vth_p,  g_Vth);
    cudaGetSymbolAddress((void**)&vtl_p,  g_Vtl);

    // 0) Weight transpose + split
    wsplit_kernel<<<512, 128>>>(W, W_output, ws_p, wos_p);

    // 1) QKV projection: [32768,128] @ [128,384] (HMMA)
    gemm_hmma<<<dim3(MROWS / 128, 3), 256>>>(x, ws_p, qkv_p, 384);

    // 2) Global K/V split + V transpose
    kvsplit_kernel<<<BB * HH, 256>>>(qkv_p, ksp_p, vth_p, vtl_p);

    // 3) Flash attention (HMMA, pre-split K/V, cp.async pipeline)
    attn_hmma<<<dim3(TT / 128, HH, BB), 256>>>(qkv_p, keys_length,
                                               ksp_p, vth_p, vtl_p, attn_p);

    // 4) Output projection: [32768,128] @ [128,128] (HMMA)
    gemm_hmma<<<dim3(MROWS / 128, 1), 256>>>(attn_p, wos_p, proj_p, DD);

    // 5) Residual + LayerNorm
    ln_kernel<<<MROWS / 8, 256>>>(proj_p, x, gamma, beta, out);
}

// round 6
// speedup vs baseline: 2.7118x; 1.2650x over previous
#include <cuda_runtime.h>
#include <cuda_bf16.h>
#include <cstdint>

// Problem constants
#define BB 32
#define TT 1024
#define DD 128
#define HH 4
#define DHH 32
#define MROWS (BB*TT)   // 32768

// Scratch (device globals — no allocation allowed)
__device__ __align__(16) float g_qkv[MROWS * 3 * DD];   // [32768, 384]
__device__ __align__(16) float g_attn[MROWS * DD];      // [32768, 128]
__device__ __align__(16) uint32_t g_Ws[384 * 128];      // W^T split
__device__ __align__(16) uint32_t g_WOs[128 * 128];     // Wout^T split
__device__ __align__(16) uint32_t g_Ksp[BB * HH * TT * 32];      // K split rows: 16 hi + 16 lo
__device__ __align__(16) uint32_t g_Vth[BB * HH * 32 * (TT/2)];  // V^T hi: [bh][d][jp]
__device__ __align__(16) uint32_t g_Vtl[BB * HH * 32 * (TT/2)];  // V^T lo

// ---------------------------------------------------------------------------
// helpers
// ---------------------------------------------------------------------------
__device__ __forceinline__ uint32_t smem_u32(const void* p) {
    uint32_t a;
    asm("{ .reg .u64 t; cvta.to.shared.u64 t, %1; cvt.u32.u64 %0, t; }"
        : "=r"(a) : "l"(p));
    return a;
}

__device__ __forceinline__ uint32_t split_pack(float x) {
    __nv_bfloat16 h = __float2bfloat16(x);
    float r = x - __bfloat162float(h);
    __nv_bfloat16 l = __float2bfloat16(r);
    return (uint32_t)__bfloat16_as_ushort(h) | ((uint32_t)__bfloat16_as_ushort(l) << 16);
}

// pack two floats as bf16x2: low 16 = x (even index), high 16 = y (odd index)
__device__ __forceinline__ uint32_t pack_bf16x2(float x, float y) {
    uint32_t d;
    asm("cvt.rn.bf16x2.f32 %0, %1, %2;" : "=r"(d) : "f"(y), "f"(x));
    return d;
}

__device__ __forceinline__ float ex2f(float x) {
    float r;
    asm("ex2.approx.ftz.f32 %0, %1;" : "=f"(r) : "f"(x));
    return r;
}

#define LDSM_X4(r0, r1, r2, r3, addr) \
    asm volatile("ldmatrix.sync.aligned.m8n8.x4.shared.b16 {%0,%1,%2,%3}, [%4];" \
                 : "=r"(r0), "=r"(r1), "=r"(r2), "=r"(r3) : "r"(addr))

#define LDSM_X2(r0, r1, addr) \
    asm volatile("ldmatrix.sync.aligned.m8n8.x2.shared.b16 {%0,%1}, [%2];" \
                 : "=r"(r0), "=r"(r1) : "r"(addr))

#define MMA_16816(c, a, b) \
    asm volatile("mma.sync.aligned.m16n8k16.row.col.f32.bf16.bf16.f32 " \
                 "{%0,%1,%2,%3}, {%4,%5,%6,%7}, {%8,%9}, {%0,%1,%2,%3};" \
                 : "+f"((c)[0]), "+f"((c)[1]), "+f"((c)[2]), "+f"((c)[3]) \
                 : "r"((a)[0]), "r"((a)[1]), "r"((a)[2]), "r"((a)[3]), \
                   "r"((b)[0]), "r"((b)[1]))

#define CP_ASYNC16(dst, src) \
    asm volatile("cp.async.cg.shared.global [%0], [%1], 16;" :: "r"(dst), "l"(src))
#define CP_COMMIT() asm volatile("cp.async.commit_group;" ::: "memory")
#define CP_WAIT(n)  asm volatile("cp.async.wait_group %0;" :: "n"(n) : "memory")

// ---------------------------------------------------------------------------
// Prepass 1: transpose W / W_output and split fp32 -> (hi,lo) bf16 pairs.
// ---------------------------------------------------------------------------
__global__ void wsplit_kernel(const float* __restrict__ W,
                              const float* __restrict__ Wo,
                              uint32_t* __restrict__ Ws,
                              uint32_t* __restrict__ WOs) {
    int n = blockIdx.x;
    int k = threadIdx.x;
    if (n < 384) {
        Ws[n * 128 + k] = split_pack(W[k * 384 + n]);
    } else {
        int nn = n - 384;
        WOs[nn * 128 + k] = split_pack(Wo[k * 128 + nn]);
    }
}

// ---------------------------------------------------------------------------
// Prepass 2 (coalesced): K row split + V transpose-split via smem tile.
// grid (128 bh, 8 j-blocks of 128), 256 threads.
// ---------------------------------------------------------------------------
__global__ __launch_bounds__(256) void kvsplit_kernel(
    const float* __restrict__ qkv, uint32_t* __restrict__ Ksp,
    uint32_t* __restrict__ Vth, uint32_t* __restrict__ Vtl) {
    __shared__ float sv[128][33];

    const int bh = blockIdx.x;
    const int b = bh >> 2, h = bh & 3;
    const int jb0 = blockIdx.y * 128;
    const int tid = threadIdx.x;

    // ---- K: rows coalesced (16 threads cover one 128B row segment) ----
#pragma unroll
    for (int r = 0; r < 8; r++) {
        int idx = tid + r * 256;              // 0..2047
        int j = idx >> 4, dp = idx & 15;
        const float* p = &qkv[((size_t)(b * TT + jb0 + j)) * 384 + 128 + h * 32 + dp * 2];
        float x = p[0], y = p[1];
        uint32_t hi = pack_bf16x2(x, y);
        float hx = __uint_as_float(hi << 16);
        float hy = __uint_as_float(hi & 0xffff0000u);
        uint32_t* o = &Ksp[((size_t)(bh * TT + jb0 + j)) * 32];
        o[dp] = hi;
        o[16 + dp] = pack_bf16x2(x - hx, y - hy);
    }

    // ---- V: coalesced load into smem tile ----
#pragma unroll
    for (int r = 0; r < 16; r++) {
        int idx = tid + r * 256;              // 0..4095
        int j = idx >> 5, d = idx & 31;
        sv[j][d] = qkv[((size_t)(b * TT + jb0 + j)) * 384 + 256 + h * 32 + d];
    }
    __syncthreads();

    // ---- transposed, split, coalesced store along jp ----
#pragma unroll
    for (int r = 0; r < 8; r++) {
        int idx = tid + r * 256;              // 0..2047
        int d = idx >> 6, jp = idx & 63;
        float v0 = sv[jp * 2][d], v1 = sv[jp * 2 + 1][d];
        uint32_t hi = pack_bf16x2(v0, v1);
        float h0 = __uint_as_float(hi << 16);
        float h1 = __uint_as_float(hi & 0xffff0000u);
        size_t o = (size_t)(bh * 32 + d) * (TT / 2) + (jb0 >> 1) + jp;
        Vth[o] = hi;
        Vtl[o] = pack_bf16x2(v0 - h0, v1 - h1);
    }
}

// ---------------------------------------------------------------------------
// HMMA GEMM (QKV): C[M, Ntot] = A[M,128] * W[128,Ntot] via bf16 hi/lo split.
// ---------------------------------------------------------------------------
__global__ __launch_bounds__(256) void gemm_hmma(
    const float* __restrict__ A, const uint32_t* __restrict__ Bg,
    float* __restrict__ C, int Ntot) {
    __shared__ uint32_t As_s[128 * 36];
    __shared__ uint32_t Bs_s[128 * 36];

    const int tid = threadIdx.x;
    const int wid = tid >> 5;
    const int lane = tid & 31;
    const int wm = wid >> 2;
    const int wn = wid & 3;
    const int m0 = blockIdx.x * 128;
    const int n0 = blockIdx.y * 128;

    const uint32_t sa = smem_u32(As_s);
    const uint32_t sb = smem_u32(Bs_s);

    float acc[4][4][4];
#pragma unroll
    for (int i = 0; i < 4; i++)
#pragma unroll
        for (int j = 0; j < 4; j++)
#pragma unroll
            for (int q = 0; q < 4; q++) acc[i][j][q] = 0.f;

    const int a_row = lane & 15;
    const int a_koff = (lane >> 4) * 4;
    const int b_row = lane & 7;
    const int b_koff = ((lane >> 3) & 1) * 4;

    for (int ch = 0; ch < 4; ch++) {
        const int kc = ch * 32;
#pragma unroll
        for (int r = 0; r < 4; r++) {
            int idx = tid + r * 256;
            int row = idx >> 3, c4 = idx & 7;
            float4 v = *(const float4*)&A[(size_t)(m0 + row) * 128 + kc + c4 * 4];
            uint32_t* d = &As_s[row * 36 + c4 * 4];
            d[0] = split_pack(v.x); d[1] = split_pack(v.y);
            d[2] = split_pack(v.z); d[3] = split_pack(v.w);
        }
#pragma unroll
        for (int r = 0; r < 4; r++) {
            int idx = tid + r * 256;
            int row = idx >> 3, c16 = idx & 7;
            uint4 v = *(const uint4*)&Bg[(size_t)(n0 + row) * 128 + kc + c16 * 4];
            uint32_t* d = &Bs_s[row * 36 + c16 * 4];
            d[0] = v.x; d[1] = v.y; d[2] = v.z; d[3] = v.w;
        }
        __syncthreads();

#pragma unroll
        for (int s = 0; s < 4; s++) {
            uint32_t af[4][4];
#pragma unroll
            for (int tm = 0; tm < 4; tm++) {
                uint32_t addr = sa + (uint32_t)(((wm * 64 + tm * 16 + a_row) * 36 +
                                                 s * 8 + a_koff) * 4);
                LDSM_X4(af[tm][0], af[tm][1], af[tm][2], af[tm][3], addr);
            }
            uint32_t bf[4][2];
#pragma unroll
            for (int tn = 0; tn < 4; tn++) {
                uint32_t addr = sb + (uint32_t)(((wn * 32 + tn * 8 + b_row) * 36 +
                                                 s * 8 + b_koff) * 4);
                LDSM_X2(bf[tn][0], bf[tn][1], addr);
            }
#pragma unroll
            for (int tm = 0; tm < 4; tm++)
#pragma unroll
                for (int tn = 0; tn < 4; tn++)
                    MMA_16816(acc[tm][tn], af[tm], bf[tn]);
        }
        __syncthreads();
    }

    const int er = lane >> 2;
    const int ec = (lane & 3) * 2;
#pragma unroll
    for (int tm = 0; tm < 4; tm++) {
#pragma unroll
        for (int tn = 0; tn < 4; tn++) {
            int row = m0 + wm * 64 + tm * 16 + er;
            int col = n0 + wn * 32 + tn * 8 + ec;
            *(float2*)&C[(size_t)row * Ntot + col] =
                make_float2(acc[tm][tn][0], acc[tm][tn][1]);
            *(float2*)&C[(size_t)(row + 8) * Ntot + col] =
                make_float2(acc[tm][tn][2], acc[tm][tn][3]);
        }
    }
}

// ---------------------------------------------------------------------------
// Fused output projection + residual + LayerNorm. Ntot = 128, n0 = 0:
// each CTA owns 128 complete rows -> CTA-level LN in the epilogue.
// ---------------------------------------------------------------------------
__global__ __launch_bounds__(256) void gemm_out_ln(
    const float* __restrict__ A, const uint32_t* __restrict__ Bg,
    const float* __restrict__ x, const float* __restrict__ gamma,
    const float* __restrict__ beta, float* __restrict__ out) {
    __shared__ uint32_t As_s[128 * 36];
    __shared__ uint32_t Bs_s[128 * 36];

    const int tid = threadIdx.x;
    const int wid = tid >> 5;
    const int lane = tid & 31;
    const int wm = wid >> 2;
    const int wn = wid & 3;
    const int m0 = blockIdx.x * 128;

    const uint32_t sa = smem_u32(As_s);
    const uint32_t sb = smem_u32(Bs_s);

    float acc[4][4][4];
#pragma unroll
    for (int i = 0; i < 4; i++)
#pragma unroll
        for (int j = 0; j < 4; j++)
#pragma unroll
            for (int q = 0; q < 4; q++) acc[i][j][q] = 0.f;

    const int a_row = lane & 15;
    const int a_koff = (lane >> 4) * 4;
    const int b_row = lane & 7;
    const int b_koff = ((lane >> 3) & 1) * 4;

    for (int ch = 0; ch < 4; ch++) {
        const int kc = ch * 32;
#pragma unroll
        for (int r = 0; r < 4; r++) {
            int idx = tid + r * 256;
            int row = idx >> 3, c4 = idx & 7;
            float4 v = *(const float4*)&A[(size_t)(m0 + row) * 128 + kc + c4 * 4];
            uint32_t* d = &As_s[row * 36 + c4 * 4];
            d[0] = split_pack(v.x); d[1] = split_pack(v.y);
            d[2] = split_pack(v.z); d[3] = split_pack(v.w);
        }
#pragma unroll
        for (int r = 0; r < 4; r++) {
            int idx = tid + r * 256;
            int row = idx >> 3, c16 = idx & 7;
            uint4 v = *(const uint4*)&Bg[(size_t)row * 128 + kc + c16 * 4];
            uint32_t* d = &Bs_s[row * 36 + c16 * 4];
            d[0] = v.x; d[1] = v.y; d[2] = v.z; d[3] = v.w;
        }
        __syncthreads();

#pragma unroll
        for (int s = 0; s < 4; s++) {
            uint32_t af[4][4];
#pragma unroll
            for (int tm = 0; tm < 4; tm++) {
                uint32_t addr = sa + (uint32_t)(((wm * 64 + tm * 16 + a_row) * 36 +
                                                 s * 8 + a_koff) * 4);
                LDSM_X4(af[tm][0], af[tm][1], af[tm][2], af[tm][3], addr);
            }
            uint32_t bf[4][2];
#pragma unroll
            for (int tn = 0; tn < 4; tn++) {
                uint32_t addr = sb + (uint32_t)(((wn * 32 + tn * 8 + b_row) * 36 +
                                                 s * 8 + b_koff) * 4);
                LDSM_X2(bf[tn][0], bf[tn][1], addr);
            }
#pragma unroll
            for (int tm = 0; tm < 4; tm++)
#pragma unroll
                for (int tn = 0; tn < 4; tn++)
                    MMA_16816(acc[tm][tn], af[tm], bf[tn]);
        }
        __syncthreads();
    }

    // ---- epilogue: residual + LN ----
    const int er = lane >> 2;
    const int ec = (lane & 3) * 2;

    // add residual x
#pragma unroll
    for (int tm = 0; tm < 4; tm++) {
#pragma unroll
        for (int tn = 0; tn < 4; tn++) {
            int row = m0 + wm * 64 + tm * 16 + er;
            int col = wn * 32 + tn * 8 + ec;
            float2 x0 = *(const float2*)&x[(size_t)row * 128 + col];
            float2 x1 = *(const float2*)&x[(size_t)(row + 8) * 128 + col];
            acc[tm][tn][0] += x0.x; acc[tm][tn][1] += x0.y;
            acc[tm][tn][2] += x1.x; acc[tm][tn][3] += x1.y;
        }
    }

    // per-row partial sums: quad shuffle -> smem [wn][128] float2 (sum, sq)
    float2* red = (float2*)As_s;   // 4*128 float2 = 4KB, smem reuse after sync
#pragma unroll
    for (int tm = 0; tm < 4; tm++) {
        float s0 = 0.f, q0 = 0.f, s1 = 0.f, q1 = 0.f;
#pragma unroll
        for (int tn = 0; tn < 4; tn++) {
            s0 += acc[tm][tn][0] + acc[tm][tn][1];
            q0 += acc[tm][tn][0] * acc[tm][tn][0] + acc[tm][tn][1] * acc[tm][tn][1];
            s1 += acc[tm][tn][2] + acc[tm][tn][3];
            q1 += acc[tm][tn][2] * acc[tm][tn][2] + acc[tm][tn][3] * acc[tm][tn][3];
        }
#pragma unroll
        for (int off = 1; off < 4; off <<= 1) {
            s0 += __shfl_xor_sync(0xffffffffu, s0, off);
            q0 += __shfl_xor_sync(0xffffffffu, q0, off);
            s1 += __shfl_xor_sync(0xffffffffu, s1, off);
            q1 += __shfl_xor_sync(0xffffffffu, q1, off);
        }
        if ((lane & 3) == 0) {
            int rl = wm * 64 + tm * 16 + er;
            red[wn * 128 + rl] = make_float2(s0, q0);
            red[wn * 128 + rl + 8] = make_float2(s1, q1);
        }
    }
    __syncthreads();

    // load gamma/beta for this lane's columns
    float2 gm[4], bt[4];
#pragma unroll
    for (int tn = 0; tn < 4; tn++) {
        int col = wn * 32 + tn * 8 + ec;
        gm[tn] = *(const float2*)&gamma[col];
        bt[tn] = *(const float2*)&beta[col];
    }

#pragma unroll
    for (int tm = 0; tm < 4; tm++) {
        int rl = wm * 64 + tm * 16 + er;
        float s0 = 0.f, q0 = 0.f, s1 = 0.f, q1 = 0.f;
#pragma unroll
        for (int w = 0; w < 4; w++) {
            float2 p0 = red[w * 128 + rl];
            float2 p1 = red[w * 128 + rl + 8];
            s0 += p0.x; q0 += p0.y;
            s1 += p1.x; q1 += p1.y;
        }
        float mean0 = s0 * (1.f / 128.f);
        float var0 = q0 * (1.f / 128.f) - mean0 * mean0;
        float rstd0 = rsqrtf(var0 + 1e-9f);
        float mean1 = s1 * (1.f / 128.f);
        float var1 = q1 * (1.f / 128.f) - mean1 * mean1;
        float rstd1 = rsqrtf(var1 + 1e-9f);

        int row = m0 + rl;
#pragma unroll
        for (int tn = 0; tn < 4; tn++) {
            int col = wn * 32 + tn * 8 + ec;
            float2 o0 = make_float2(
                (acc[tm][tn][0] - mean0) * rstd0 * gm[tn].x + bt[tn].x,
                (acc[tm][tn][1] - mean0) * rstd0 * gm[tn].y + bt[tn].y);
            float2 o1 = make_float2(
                (acc[tm][tn][2] - mean1) * rstd1 * gm[tn].x + bt[tn].x,
                (acc[tm][tn][3] - mean1) * rstd1 * gm[tn].y + bt[tn].y);
            *(float2*)&out[(size_t)row * 128 + col] = o0;
            *(float2*)&out[(size_t)(row + 8) * 128 + col] = o1;
        }
    }
}

// ---------------------------------------------------------------------------
// HMMA flash attention: pre-split K/V, cp.async double-buffering, X4 loads,
// heavy-first q-block order, per-ks-pair P streaming (reg pressure).
// ---------------------------------------------------------------------------
__global__ __launch_bounds__(256, 3) void attn_hmma(
    const float* __restrict__ qkv, const int* __restrict__ keys_length,
    const uint32_t* __restrict__ Ksp, const uint32_t* __restrict__ Vth,
    const uint32_t* __restrict__ Vtl, float* __restrict__ out) {
    __shared__ __align__(16) uint32_t S[9216];

    const int q0 = (int)(gridDim.x - 1 - blockIdx.x) * 128;  // heavy-first
    const int h = blockIdx.y;
    const int b = blockIdx.z;
    const int bh = b * HH + h;
    const int tid = threadIdx.x;
    const int wid = tid >> 5;
    const int lane = tid & 31;
    const uint32_t sS = smem_u32(S);

    const int L = keys_length[b];
    const int kend = min(q0 + 128, L);
    const int ntiles = (kend + 63) >> 6;

    const uint32_t* kbase = Ksp + (size_t)(bh * TT) * 32;
    const uint32_t* vhbase = Vth + (size_t)(bh * 32) * (TT / 2);
    const uint32_t* vlbase = Vtl + (size_t)(bh * 32) * (TT / 2);

    // ---- prefetch tile 0 into buf0 ----
    {
        const uint32_t sk = sS;
        const uint32_t* kt = kbase;
#pragma unroll
        for (int r = 0; r < 2; r++) {
            int idx = tid + r * 256;
            int row = idx >> 3, c4 = idx & 7;
            CP_ASYNC16(sk + (uint32_t)((row * 36 + c4 * 4) * 4), kt + row * 32 + c4 * 4);
        }
        {
            int d = tid >> 3, c4 = tid & 7;
            CP_ASYNC16(sk + (uint32_t)((2304 + d * 36 + c4 * 4) * 4),
                       vhbase + (size_t)d * (TT / 2) + c4 * 4);
            CP_ASYNC16(sk + (uint32_t)((3456 + d * 36 + c4 * 4) * 4),
                       vlbase + (size_t)d * (TT / 2) + c4 * 4);
        }
        CP_COMMIT();
    }

    // ---- stage Q split into buf1 region ----
    const float qscale = 0.17677669529663687f * 1.4426950408889634f;
    for (int idx = tid; idx < 128 * 16; idx += 256) {
        int row = idx >> 4, dp = idx & 15;
        const float* p = &qkv[((size_t)(b * TT + q0 + row)) * 384 + h * 32 + dp * 2];
        float x = p[0] * qscale, y = p[1] * qscale;
        uint32_t hi = pack_bf16x2(x, y);
        float hx = __uint_as_float(hi << 16);
        float hy = __uint_as_float(hi & 0xffff0000u);
        S[4608 + row * 36 + dp] = hi;
        S[4608 + row * 36 + 16 + dp] = pack_bf16x2(x - hx, y - hy);
    }
    __syncthreads();

    // ---- Q A-fragments (registers, reused every tile) ----
    const int a_row = lane & 15;
    const int a_koff = (lane >> 4) * 4;
    uint32_t aH[2][4], aL[2][4];
#pragma unroll
    for (int ks = 0; ks < 2; ks++) {
        uint32_t addr = sS + (uint32_t)((4608 + (wid * 16 + a_row) * 36 + ks * 8 + a_koff) * 4);
        LDSM_X4(aH[ks][0], aH[ks][1], aH[ks][2], aH[ks][3], addr);
        LDSM_X4(aL[ks][0], aL[ks][1], aL[ks][2], aL[ks][3], addr + 64);
    }
    __syncthreads();   // Q fragments live in registers; buf1 reusable

    float o[4][4];
#pragma unroll
    for (int nt = 0; nt < 4; nt++)
#pragma unroll
        for (int c = 0; c < 4; c++) o[nt][c] = 0.f;
    float m0 = -1e30f, m1 = -1e30f, l0 = 0.f, l1 = 0.f;

    const int r0 = q0 + wid * 16 + (lane >> 2);
    const int r1 = r0 + 8;
    const int rmax = q0 + wid * 16 + 15;
    const int b_row = lane & 7;
    const int b_k4 = (lane >> 3) * 4;

    for (int t = 0; t < ntiles; t++) {
        if (t + 1 < ntiles) {
            const uint32_t sk = sS + (uint32_t)(((t + 1) & 1) * 4608 * 4);
            const uint32_t* kt = kbase + (size_t)(t + 1) * 64 * 32;
#pragma unroll
            for (int r = 0; r < 2; r++) {
                int idx = tid + r * 256;
                int row = idx >> 3, c4 = idx & 7;
                CP_ASYNC16(sk + (uint32_t)((row * 36 + c4 * 4) * 4), kt + row * 32 + c4 * 4);
            }
            {
                int d = tid >> 3, c4 = tid & 7;
                CP_ASYNC16(sk + (uint32_t)((2304 + d * 36 + c4 * 4) * 4),
                           vhbase + (size_t)d * (TT / 2) + (t + 1) * 32 + c4 * 4);
                CP_ASYNC16(sk + (uint32_t)((3456 + d * 36 + c4 * 4) * 4),
                           vlbase + (size_t)d * (TT / 2) + (t + 1) * 32 + c4 * 4);
            }
            CP_COMMIT();
            CP_WAIT(1);
        } else {
            CP_WAIT(0);
        }
        __syncthreads();

        const int j0 = t * 64;
        if (j0 <= rmax) {
            const uint32_t skb = sS + (uint32_t)((t & 1) * 4608 * 4);

            // ---- scores S = Q K^T (3-term split) ----
            float s[8][4];
#pragma unroll
            for (int tt = 0; tt < 8; tt++)
#pragma unroll
                for (int c = 0; c < 4; c++) s[tt][c] = 0.f;

#pragma unroll
            for (int tt = 0; tt < 8; tt++) {
                uint32_t krow = skb + (uint32_t)(((tt * 8 + b_row) * 36 + b_k4) * 4);
                uint32_t bh0[2], bh1[2], bl0[2], bl1[2];
                LDSM_X4(bh0[0], bh0[1], bh1[0], bh1[1], krow);
                LDSM_X4(bl0[0], bl0[1], bl1[0], bl1[1], krow + 64);
                MMA_16816(s[tt], aH[0], bh0);
                MMA_16816(s[tt], aH[1], bh1);
                MMA_16816(s[tt], aL[0], bh0);
                MMA_16816(s[tt], aL[1], bh1);
                MMA_16816(s[tt], aH[0], bl0);
                MMA_16816(s[tt], aH[1], bl1);
            }

            // ---- masking (boundary tiles only) ----
            const bool needMask = (j0 + 64 > L) || (j0 + 64 > q0 + wid * 16 + 1);
            if (needMask) {
#pragma unroll
                for (int tt = 0; tt < 8; tt++) {
#pragma unroll
                    for (int c = 0; c < 2; c++) {
                        int j = j0 + tt * 8 + (lane & 3) * 2 + c;
                        if (j > r0 || j >= L) s[tt][c] = -1e30f;
                        if (j > r1 || j >= L) s[tt][2 + c] = -1e30f;
                    }
                }
            }

            // ---- online softmax (exp2 domain) ----
            float mt0 = -1e30f, mt1 = -1e30f;
#pragma unroll
            for (int tt = 0; tt < 8; tt++) {
                mt0 = fmaxf(mt0, fmaxf(s[tt][0], s[tt][1]));
                mt1 = fmaxf(mt1, fmaxf(s[tt][2], s[tt][3]));
            }
            mt0 = fmaxf(mt0, __shfl_xor_sync(0xffffffffu, mt0, 1));
            mt0 = fmaxf(mt0, __shfl_xor_sync(0xffffffffu, mt0, 2));
            mt1 = fmaxf(mt1, __shfl_xor_sync(0xffffffffu, mt1, 1));
            mt1 = fmaxf(mt1, __shfl_xor_sync(0xffffffffu, mt1, 2));

            float mn0 = fmaxf(m0, mt0), mn1 = fmaxf(m1, mt1);
            float corr0 = ex2f(m0 - mn0), corr1 = ex2f(m1 - mn1);
            m0 = mn0; m1 = mn1;

            float ps0 = 0.f, ps1 = 0.f;
#pragma unroll
            for (int tt = 0; tt < 8; tt++) {
                s[tt][0] = ex2f(s[tt][0] - mn0);
                s[tt][1] = ex2f(s[tt][1] - mn0);
                s[tt][2] = ex2f(s[tt][2] - mn1);
                s[tt][3] = ex2f(s[tt][3] - mn1);
                ps0 += s[tt][0] + s[tt][1];
                ps1 += s[tt][2] + s[tt][3];
            }
            ps0 += __shfl_xor_sync(0xffffffffu, ps0, 1);
            ps0 += __shfl_xor_sync(0xffffffffu, ps0, 2);
            ps1 += __shfl_xor_sync(0xffffffffu, ps1, 1);
            ps1 += __shfl_xor_sync(0xffffffffu, ps1, 2);
            l0 = l0 * corr0 + ps0;
            l1 = l1 * corr1 + ps1;

#pragma unroll
            for (int nt = 0; nt < 4; nt++) {
                o[nt][0] *= corr0; o[nt][1] *= corr0;
                o[nt][2] *= corr1; o[nt][3] *= corr1;
            }

            // ---- PV: stream P per ks-pair (halves P register footprint) ----
            const uint32_t svhb = skb + 2304 * 4;
            const uint32_t svlb = skb + 3456 * 4;
#pragma unroll
            for (int ksp = 0; ksp < 2; ksp++) {
                uint32_t ph2[2][4], pl2[2][4];
#pragma unroll
                for (int k2 = 0; k2 < 2; k2++) {
                    const int t0 = 4 * ksp + 2 * k2, t1 = t0 + 1;
                    float v[8] = {s[t0][0], s[t0][1], s[t0][2], s[t0][3],
                                  s[t1][0], s[t1][1], s[t1][2], s[t1][3]};
#pragma unroll
                    for (int g = 0; g < 4; g++) {
                        uint32_t hi = pack_bf16x2(v[g * 2], v[g * 2 + 1]);
                        float h0 = __uint_as_float(hi << 16);
                        float h1 = __uint_as_float(hi & 0xffff0000u);
                        ph2[k2][g] = hi;
                        pl2[k2][g] = pack_bf16x2(v[g * 2] - h0, v[g * 2 + 1] - h1);
                    }
                }
#pragma unroll
                for (int nt = 0; nt < 4; nt++) {
                    uint32_t voff = (uint32_t)(((nt * 8 + b_row) * 36 + b_k4) * 4) +
                                    (uint32_t)(ksp * 64);
                    uint32_t bvh[2][2], bvl[2][2];
                    LDSM_X4(bvh[0][0], bvh[0][1], bvh[1][0], bvh[1][1], svhb + voff);
                    LDSM_X4(bvl[0][0], bvl[0][1], bvl[1][0], bvl[1][1], svlb + voff);
#pragma unroll
                    for (int k2 = 0; k2 < 2; k2++) {
                        MMA_16816(o[nt], ph2[k2], bvh[k2]);
                        MMA_16816(o[nt], pl2[k2], bvh[k2]);
                        MMA_16816(o[nt], ph2[k2], bvl[k2]);
                    }
                }
            }
        }
        __syncthreads();
    }

    // ---- epilogue ----
    const float inv0 = 1.f / l0, inv1 = 1.f / l1;
#pragma unroll
    for (int nt = 0; nt < 4; nt++) {
        int d = h * 32 + nt * 8 + (lane & 3) * 2;
        *(float2*)&out[((size_t)(b * TT + r0)) * DD + d] =
            make_float2(o[nt][0] * inv0, o[nt][1] * inv0);
        *(float2*)&out[((size_t)(b * TT + r1)) * DD + d] =
            make_float2(o[nt][2] * inv1, o[nt][3] * inv1);
    }
}

// ---------------------------------------------------------------------------
extern "C" void kernel_launch(void* const* d_in, const int* in_sizes, int n_in,
                              void* d_out, int out_size) {
    const float* x           = (const float*)d_in[0];
    const int*   keys_length = (const int*)d_in[1];
    const float* W           = (const float*)d_in[2];
    const float* W_output    = (const float*)d_in[3];
    const float* gamma       = (const float*)d_in[4];
    const float* beta        = (const float*)d_in[5];
    float* out = (float*)d_out;

    float *qkv_p, *attn_p;
    uint32_t *ws_p, *wos_p, *ksp_p, *vth_p, *vtl_p;
    cudaGetSymbolAddress((void**)&qkv_p,  g_qkv);
    cudaGetSymbolAddress((void**)&attn_p, g_attn);
    cudaGetSymbolAddress((void**)&ws_p,   g_Ws);
    cudaGetSymbolAddress((void**)&wos_p,  g_WOs);
    cudaGetSymbolAddress((void**)&ksp_p,  g_Ksp);
    cudaGetSymbolAddress((void**)&vth_p,  g_Vth);
    cudaGetSymbolAddress((void**)&vtl_p,  g_Vtl);

    // 0) Weight transpose + split
    wsplit_kernel<<<512, 128>>>(W, W_output, ws_p, wos_p);

    // 1) QKV projection: [32768,128] @ [128,384] (HMMA)
    gemm_hmma<<<dim3(MROWS / 128, 3), 256>>>(x, ws_p, qkv_p, 384);

    // 2) Global K/V split + V transpose (coalesced)
    kvsplit_kernel<<<dim3(BB * HH, 8), 256>>>(qkv_p, ksp_p, vth_p, vtl_p);

    // 3) Flash attention (HMMA)
    attn_hmma<<<dim3(TT / 128, HH, BB), 256>>>(qkv_p, keys_length,
                                               ksp_p, vth_p, vtl_p, attn_p);

    // 4) Output projection + residual + LayerNorm (fused)
    gemm_out_ln<<<MROWS / 128, 256>>>(attn_p, wos_p, x, gamma, beta, out);
}

// round 7
// speedup vs baseline: 3.2525x; 1.1994x over previous
#include <cuda_runtime.h>
#include <cuda_bf16.h>
#include <cstdint>

// Problem constants
#define BB 32
#define TT 1024
#define DD 128
#define HH 4
#define DHH 32
#define MROWS (BB*TT)   // 32768

// Scratch (device globals — no allocation allowed)
__device__ __align__(16) float g_qkv[MROWS * 3 * DD];   // only V third used now
__device__ __align__(16) float g_attn[MROWS * DD];      // [32768, 128]
__device__ __align__(16) uint32_t g_Ws[384 * 128];      // W^T split
__device__ __align__(16) uint32_t g_WOs[128 * 128];     // Wout^T split
__device__ __align__(16) uint32_t g_Qsp[MROWS * HH * 32];        // Q split (scaled): [row][h][16hi+16lo]
__device__ __align__(16) uint32_t g_Ksp[BB * HH * TT * 32];      // K split rows: 16 hi + 16 lo
__device__ __align__(16) uint32_t g_Vth[BB * HH * 32 * (TT/2)];  // V^T hi: [bh][d][jp]
__device__ __align__(16) uint32_t g_Vtl[BB * HH * 32 * (TT/2)];  // V^T lo

// ---------------------------------------------------------------------------
// helpers
// ---------------------------------------------------------------------------
__device__ __forceinline__ uint32_t smem_u32(const void* p) {
    uint32_t a;
    asm("{ .reg .u64 t; cvta.to.shared.u64 t, %1; cvt.u32.u64 %0, t; }"
        : "=r"(a) : "l"(p));
    return a;
}

__device__ __forceinline__ uint32_t split_pack(float x) {
    __nv_bfloat16 h = __float2bfloat16(x);
    float r = x - __bfloat162float(h);
    __nv_bfloat16 l = __float2bfloat16(r);
    return (uint32_t)__bfloat16_as_ushort(h) | ((uint32_t)__bfloat16_as_ushort(l) << 16);
}

// pack two floats as bf16x2: low 16 = x (even index), high 16 = y (odd index)
__device__ __forceinline__ uint32_t pack_bf16x2(float x, float y) {
    uint32_t d;
    asm("cvt.rn.bf16x2.f32 %0, %1, %2;" : "=r"(d) : "f"(y), "f"(x));
    return d;
}

// pack pair (x,y) into hi bf16x2 + lo bf16x2
__device__ __forceinline__ void pair_split(float x, float y,
                                           uint32_t& hi, uint32_t& lo) {
    hi = pack_bf16x2(x, y);
    float hx = __uint_as_float(hi << 16);
    float hy = __uint_as_float(hi & 0xffff0000u);
    lo = pack_bf16x2(x - hx, y - hy);
}

__device__ __forceinline__ float ex2f(float x) {
    float r;
    asm("ex2.approx.ftz.f32 %0, %1;" : "=f"(r) : "f"(x));
    return r;
}

#define LDSM_X4(r0, r1, r2, r3, addr) \
    asm volatile("ldmatrix.sync.aligned.m8n8.x4.shared.b16 {%0,%1,%2,%3}, [%4];" \
                 : "=r"(r0), "=r"(r1), "=r"(r2), "=r"(r3) : "r"(addr))

#define LDSM_X2(r0, r1, addr) \
    asm volatile("ldmatrix.sync.aligned.m8n8.x2.shared.b16 {%0,%1}, [%2];" \
                 : "=r"(r0), "=r"(r1) : "r"(addr))

#define MMA_16816(c, a, b) \
    asm volatile("mma.sync.aligned.m16n8k16.row.col.f32.bf16.bf16.f32 " \
                 "{%0,%1,%2,%3}, {%4,%5,%6,%7}, {%8,%9}, {%0,%1,%2,%3};" \
                 : "+f"((c)[0]), "+f"((c)[1]), "+f"((c)[2]), "+f"((c)[3]) \
                 : "r"((a)[0]), "r"((a)[1]), "r"((a)[2]), "r"((a)[3]), \
                   "r"((b)[0]), "r"((b)[1]))

#define CP_ASYNC16(dst, src) \
    asm volatile("cp.async.cg.shared.global [%0], [%1], 16;" :: "r"(dst), "l"(src))
#define CP_COMMIT() asm volatile("cp.async.commit_group;" ::: "memory")
#define CP_WAIT(n)  asm volatile("cp.async.wait_group %0;" :: "n"(n) : "memory")

// ---------------------------------------------------------------------------
// Prepass 1: transpose W / W_output and split fp32 -> (hi,lo) bf16 pairs.
// ---------------------------------------------------------------------------
__global__ void wsplit_kernel(const float* __restrict__ W,
                              const float* __restrict__ Wo,
                              uint32_t* __restrict__ Ws,
                              uint32_t* __restrict__ WOs) {
    int n = blockIdx.x;
    int k = threadIdx.x;
    if (n < 384) {
        Ws[n * 128 + k] = split_pack(W[k * 384 + n]);
    } else {
        int nn = n - 384;
        WOs[nn * 128 + k] = split_pack(Wo[k * 128 + nn]);
    }
}

// ---------------------------------------------------------------------------
// V transpose-split (V third of g_qkv -> Vth/Vtl). grid (128 bh, 8 j-blocks).
// ---------------------------------------------------------------------------
__global__ __launch_bounds__(256) void vsplit_kernel(
    const float* __restrict__ qkv,
    uint32_t* __restrict__ Vth, uint32_t* __restrict__ Vtl) {
    __shared__ float sv[128][33];

    const int bh = blockIdx.x;
    const int b = bh >> 2, h = bh & 3;
    const int jb0 = blockIdx.y * 128;
    const int tid = threadIdx.x;

#pragma unroll
    for (int r = 0; r < 16; r++) {
        int idx = tid + r * 256;              // 0..4095
        int j = idx >> 5, d = idx & 31;
        sv[j][d] = qkv[((size_t)(b * TT + jb0 + j)) * 384 + 256 + h * 32 + d];
    }
    __syncthreads();

#pragma unroll
    for (int r = 0; r < 8; r++) {
        int idx = tid + r * 256;              // 0..2047
        int d = idx >> 6, jp = idx & 63;
        uint32_t hi, lo;
        pair_split(sv[jp * 2][d], sv[jp * 2 + 1][d], hi, lo);
        size_t o = (size_t)(bh * 32 + d) * (TT / 2) + (jb0 >> 1) + jp;
        Vth[o] = hi;
        Vtl[o] = lo;
    }
}

// ---------------------------------------------------------------------------
// QKV HMMA GEMM with fused Q/K splitting epilogue.
// blockIdx.y: 0=Q (scaled, split -> Qsp), 1=K (split -> Ksp), 2=V (fp32 -> qkv).
// ---------------------------------------------------------------------------
__global__ __launch_bounds__(256) void gemm_qkv(
    const float* __restrict__ A, const uint32_t* __restrict__ Bg,
    uint32_t* __restrict__ Qsp, uint32_t* __restrict__ Ksp,
    float* __restrict__ Vout) {
    __shared__ uint32_t As_s[128 * 36];
    __shared__ uint32_t Bs_s[128 * 36];

    const int tid = threadIdx.x;
    const int wid = tid >> 5;
    const int lane = tid & 31;
    const int wm = wid >> 2;
    const int wn = wid & 3;
    const int m0 = blockIdx.x * 128;
    const int y = blockIdx.y;
    const int n0 = y * 128;

    const uint32_t sa = smem_u32(As_s);
    const uint32_t sb = smem_u32(Bs_s);

    float acc[4][4][4];
#pragma unroll
    for (int i = 0; i < 4; i++)
#pragma unroll
        for (int j = 0; j < 4; j++)
#pragma unroll
            for (int q = 0; q < 4; q++) acc[i][j][q] = 0.f;

    const int a_row = lane & 15;
    const int a_koff = (lane >> 4) * 4;
    const int b_row = lane & 7;
    const int b_koff = ((lane >> 3) & 1) * 4;

    for (int ch = 0; ch < 4; ch++) {
        const int kc = ch * 32;
#pragma unroll
        for (int r = 0; r < 4; r++) {
            int idx = tid + r * 256;
            int row = idx >> 3, c4 = idx & 7;
            float4 v = *(const float4*)&A[(size_t)(m0 + row) * 128 + kc + c4 * 4];
            uint32_t* d = &As_s[row * 36 + c4 * 4];
            d[0] = split_pack(v.x); d[1] = split_pack(v.y);
            d[2] = split_pack(v.z); d[3] = split_pack(v.w);
        }
#pragma unroll
        for (int r = 0; r < 4; r++) {
            int idx = tid + r * 256;
            int row = idx >> 3, c16 = idx & 7;
            uint4 v = *(const uint4*)&Bg[(size_t)(n0 + row) * 128 + kc + c16 * 4];
            uint32_t* d = &Bs_s[row * 36 + c16 * 4];
            d[0] = v.x; d[1] = v.y; d[2] = v.z; d[3] = v.w;
        }
        __syncthreads();

#pragma unroll
        for (int s = 0; s < 4; s++) {
            uint32_t af[4][4];
#pragma unroll
            for (int tm = 0; tm < 4; tm++) {
                uint32_t addr = sa + (uint32_t)(((wm * 64 + tm * 16 + a_row) * 36 +
                                                 s * 8 + a_koff) * 4);
                LDSM_X4(af[tm][0], af[tm][1], af[tm][2], af[tm][3], addr);
            }
            uint32_t bf[4][2];
#pragma unroll
            for (int tn = 0; tn < 4; tn++) {
                uint32_t addr = sb + (uint32_t)(((wn * 32 + tn * 8 + b_row) * 36 +
                                                 s * 8 + b_koff) * 4);
                LDSM_X2(bf[tn][0], bf[tn][1], addr);
            }
#pragma unroll
            for (int tm = 0; tm < 4; tm++)
#pragma unroll
                for (int tn = 0; tn < 4; tn++)
                    MMA_16816(acc[tm][tn], af[tm], bf[tn]);
        }
        __syncthreads();
    }

    const int er = lane >> 2;
    const int ec = (lane & 3) * 2;
    const float qscale = 0.17677669529663687f * 1.4426950408889634f;

    if (y == 2) {
        // V: plain fp32 write into the V third of g_qkv
#pragma unroll
        for (int tm = 0; tm < 4; tm++) {
#pragma unroll
            for (int tn = 0; tn < 4; tn++) {
                int row = m0 + wm * 64 + tm * 16 + er;
                int col = wn * 32 + tn * 8 + ec;
                *(float2*)&Vout[(size_t)row * 384 + 256 + col] =
                    make_float2(acc[tm][tn][0], acc[tm][tn][1]);
                *(float2*)&Vout[(size_t)(row + 8) * 384 + 256 + col] =
                    make_float2(acc[tm][tn][2], acc[tm][tn][3]);
            }
        }
    } else {
        const float sc = (y == 0) ? qscale : 1.f;
#pragma unroll
        for (int tm = 0; tm < 4; tm++) {
#pragma unroll
            for (int tn = 0; tn < 4; tn++) {
                int row = m0 + wm * 64 + tm * 16 + er;
                int col = wn * 32 + tn * 8 + ec;
                int head = col >> 5;
                int dp = (col & 31) >> 1;
                uint32_t hi0, lo0, hi1, lo1;
                pair_split(acc[tm][tn][0] * sc, acc[tm][tn][1] * sc, hi0, lo0);
                pair_split(acc[tm][tn][2] * sc, acc[tm][tn][3] * sc, hi1, lo1);
                if (y == 0) {
                    uint32_t* d0 = &Qsp[((size_t)row * 4 + head) * 32];
                    uint32_t* d1 = &Qsp[((size_t)(row + 8) * 4 + head) * 32];
                    d0[dp] = hi0; d0[16 + dp] = lo0;
                    d1[dp] = hi1; d1[16 + dp] = lo1;
                } else {
                    int bb = row >> 10;
                    int t0 = row & 1023;
                    uint32_t* d0 = &Ksp[(((size_t)bb * 4 + head) * 1024 + t0) * 32];
                    uint32_t* d1 = d0 + 8 * 32;
                    d0[dp] = hi0; d0[16 + dp] = lo0;
                    d1[dp] = hi1; d1[16 + dp] = lo1;
                }
            }
        }
    }
}

// ---------------------------------------------------------------------------
// Fused output projection + residual + LayerNorm.
// ---------------------------------------------------------------------------
__global__ __launch_bounds__(256) void gemm_out_ln(
    const float* __restrict__ A, const uint32_t* __restrict__ Bg,
    const float* __restrict__ x, const float* __restrict__ gamma,
    const float* __restrict__ beta, float* __restrict__ out) {
    __shared__ uint32_t As_s[128 * 36];
    __shared__ uint32_t Bs_s[128 * 36];

    const int tid = threadIdx.x;
    const int wid = tid >> 5;
    const int lane = tid & 31;
    const int wm = wid >> 2;
    const int wn = wid & 3;
    const int m0 = blockIdx.x * 128;

    const uint32_t sa = smem_u32(As_s);
    const uint32_t sb = smem_u32(Bs_s);

    float acc[4][4][4];
#pragma unroll
    for (int i = 0; i < 4; i++)
#pragma unroll
        for (int j = 0; j < 4; j++)
#pragma unroll
            for (int q = 0; q < 4; q++) acc[i][j][q] = 0.f;

    const int a_row = lane & 15;
    const int a_koff = (lane >> 4) * 4;
    const int b_row = lane & 7;
    const int b_koff = ((lane >> 3) & 1) * 4;

    for (int ch = 0; ch < 4; ch++) {
        const int kc = ch * 32;
#pragma unroll
        for (int r = 0; r < 4; r++) {
            int idx = tid + r * 256;
            int row = idx >> 3, c4 = idx & 7;
            float4 v = *(const float4*)&A[(size_t)(m0 + row) * 128 + kc + c4 * 4];
            uint32_t* d = &As_s[row * 36 + c4 * 4];
            d[0] = split_pack(v.x); d[1] = split_pack(v.y);
            d[2] = split_pack(v.z); d[3] = split_pack(v.w);
        }
#pragma unroll
        for (int r = 0; r < 4; r++) {
            int idx = tid + r * 256;
            int row = idx >> 3, c16 = idx & 7;
            uint4 v = *(const uint4*)&Bg[(size_t)row * 128 + kc + c16 * 4];
            uint32_t* d = &Bs_s[row * 36 + c16 * 4];
            d[0] = v.x; d[1] = v.y; d[2] = v.z; d[3] = v.w;
        }
        __syncthreads();

#pragma unroll
        for (int s = 0; s < 4; s++) {
            uint32_t af[4][4];
#pragma unroll
            for (int tm = 0; tm < 4; tm++) {
                uint32_t addr = sa + (uint32_t)(((wm * 64 + tm * 16 + a_row) * 36 +
                                                 s * 8 + a_koff) * 4);
                LDSM_X4(af[tm][0], af[tm][1], af[tm][2], af[tm][3], addr);
            }
            uint32_t bf[4][2];
#pragma unroll
            for (int tn = 0; tn < 4; tn++) {
                uint32_t addr = sb + (uint32_t)(((wn * 32 + tn * 8 + b_row) * 36 +
                                                 s * 8 + b_koff) * 4);
                LDSM_X2(bf[tn][0], bf[tn][1], addr);
            }
#pragma unroll
            for (int tm = 0; tm < 4; tm++)
#pragma unroll
                for (int tn = 0; tn < 4; tn++)
                    MMA_16816(acc[tm][tn], af[tm], bf[tn]);
        }
        __syncthreads();
    }

    // ---- epilogue: residual + LN ----
    const int er = lane >> 2;
    const int ec = (lane & 3) * 2;

#pragma unroll
    for (int tm = 0; tm < 4; tm++) {
#pragma unroll
        for (int tn = 0; tn < 4; tn++) {
            int row = m0 + wm * 64 + tm * 16 + er;
            int col = wn * 32 + tn * 8 + ec;
            float2 x0 = *(const float2*)&x[(size_t)row * 128 + col];
            float2 x1 = *(const float2*)&x[(size_t)(row + 8) * 128 + col];
            acc[tm][tn][0] += x0.x; acc[tm][tn][1] += x0.y;
            acc[tm][tn][2] += x1.x; acc[tm][tn][3] += x1.y;
        }
    }

    float2* red = (float2*)As_s;
#pragma unroll
    for (int tm = 0; tm < 4; tm++) {
        float s0 = 0.f, q0 = 0.f, s1 = 0.f, q1 = 0.f;
#pragma unroll
        for (int tn = 0; tn < 4; tn++) {
            s0 += acc[tm][tn][0] + acc[tm][tn][1];
            q0 += acc[tm][tn][0] * acc[tm][tn][0] + acc[tm][tn][1] * acc[tm][tn][1];
            s1 += acc[tm][tn][2] + acc[tm][tn][3];
            q1 += acc[tm][tn][2] * acc[tm][tn][2] + acc[tm][tn][3] * acc[tm][tn][3];
        }
#pragma unroll
        for (int off = 1; off < 4; off <<= 1) {
            s0 += __shfl_xor_sync(0xffffffffu, s0, off);
            q0 += __shfl_xor_sync(0xffffffffu, q0, off);
            s1 += __shfl_xor_sync(0xffffffffu, s1, off);
            q1 += __shfl_xor_sync(0xffffffffu, q1, off);
        }
        if ((lane & 3) == 0) {
            int rl = wm * 64 + tm * 16 + er;
            red[wn * 128 + rl] = make_float2(s0, q0);
            red[wn * 128 + rl + 8] = make_float2(s1, q1);
        }
    }
    __syncthreads();

    float2 gm[4], bt[4];
#pragma unroll
    for (int tn = 0; tn < 4; tn++) {
        int col = wn * 32 + tn * 8 + ec;
        gm[tn] = *(const float2*)&gamma[col];
        bt[tn] = *(const float2*)&beta[col];
    }

#pragma unroll
    for (int tm = 0; tm < 4; tm++) {
        int rl = wm * 64 + tm * 16 + er;
        float s0 = 0.f, q0 = 0.f, s1 = 0.f, q1 = 0.f;
#pragma unroll
        for (int w = 0; w < 4; w++) {
            float2 p0 = red[w * 128 + rl];
            float2 p1 = red[w * 128 + rl + 8];
            s0 += p0.x; q0 += p0.y;
            s1 += p1.x; q1 += p1.y;
        }
        float mean0 = s0 * (1.f / 128.f);
        float var0 = q0 * (1.f / 128.f) - mean0 * mean0;
        float rstd0 = rsqrtf(var0 + 1e-9f);
        float mean1 = s1 * (1.f / 128.f);
        float var1 = q1 * (1.f / 128.f) - mean1 * mean1;
        float rstd1 = rsqrtf(var1 + 1e-9f);

        int row = m0 + rl;
#pragma unroll
        for (int tn = 0; tn < 4; tn++) {
            int col = wn * 32 + tn * 8 + ec;
            float2 o0 = make_float2(
                (acc[tm][tn][0] - mean0) * rstd0 * gm[tn].x + bt[tn].x,
                (acc[tm][tn][1] - mean0) * rstd0 * gm[tn].y + bt[tn].y);
            float2 o1 = make_float2(
                (acc[tm][tn][2] - mean1) * rstd1 * gm[tn].x + bt[tn].x,
                (acc[tm][tn][3] - mean1) * rstd1 * gm[tn].y + bt[tn].y);
            *(float2*)&out[(size_t)row * 128 + col] = o0;
            *(float2*)&out[(size_t)(row + 8) * 128 + col] = o1;
        }
    }
}

// ---------------------------------------------------------------------------
// HMMA flash attention: pre-split Q/K/V, cp.async double-buffering, X4 loads,
// globally heavy-first 1D grid.
// ---------------------------------------------------------------------------
__global__ __launch_bounds__(256, 3) void attn_hmma(
    const uint32_t* __restrict__ Qsp, const int* __restrict__ keys_length,
    const uint32_t* __restrict__ Ksp, const uint32_t* __restrict__ Vth,
    const uint32_t* __restrict__ Vtl, float* __restrict__ out) {
    __shared__ __align__(16) uint32_t S[9216];

    // heavy-first global order: first 128 CTAs take qb=7 for all (b,h), etc.
    const int bid = blockIdx.x;
    const int q0 = (7 - (bid >> 7)) * 128;
    const int bh = bid & 127;
    const int h = bh & 3;
    const int b = bh >> 2;
    const int tid = threadIdx.x;
    const int wid = tid >> 5;
    const int lane = tid & 31;
    const uint32_t sS = smem_u32(S);

    const int L = keys_length[b];
    const int kend = min(q0 + 128, L);
    const int ntiles = (kend + 63) >> 6;

    const uint32_t* kbase = Ksp + (size_t)(bh * TT) * 32;
    const uint32_t* vhbase = Vth + (size_t)(bh * 32) * (TT / 2);
    const uint32_t* vlbase = Vtl + (size_t)(bh * 32) * (TT / 2);

    // ---- prefetch tile 0 (buf0) + pre-split Q (buf1) in one group ----
    {
        const uint32_t sk = sS;
        const uint32_t* kt = kbase;
#pragma unroll
        for (int r = 0; r < 2; r++) {
            int idx = tid + r * 256;
            int row = idx >> 3, c4 = idx & 7;
            CP_ASYNC16(sk + (uint32_t)((row * 36 + c4 * 4) * 4), kt + row * 32 + c4 * 4);
        }
        {
            int d = tid >> 3, c4 = tid & 7;
            CP_ASYNC16(sk + (uint32_t)((2304 + d * 36 + c4 * 4) * 4),
                       vhbase + (size_t)d * (TT / 2) + c4 * 4);
            CP_ASYNC16(sk + (uint32_t)((3456 + d * 36 + c4 * 4) * 4),
                       vlbase + (size_t)d * (TT / 2) + c4 * 4);
        }
#pragma unroll
        for (int r = 0; r < 4; r++) {
            int idx = tid + r * 256;          // 0..1023
            int row = idx >> 3, c4 = idx & 7;
            CP_ASYNC16(sS + (uint32_t)((4608 + row * 36 + c4 * 4) * 4),
                       Qsp + ((size_t)(b * TT + q0 + row) * 4 + h) * 32 + c4 * 4);
        }
        CP_COMMIT();
    }

    CP_WAIT(0);
    __syncthreads();

    // ---- Q A-fragments (registers, reused every tile) ----
    const int a_row = lane & 15;
    const int a_koff = (lane >> 4) * 4;
    uint32_t aH[2][4], aL[2][4];
#pragma unroll
    for (int ks = 0; ks < 2; ks++) {
        uint32_t addr = sS + (uint32_t)((4608 + (wid * 16 + a_row) * 36 + ks * 8 + a_koff) * 4);
        LDSM_X4(aH[ks][0], aH[ks][1], aH[ks][2], aH[ks][3], addr);
        LDSM_X4(aL[ks][0], aL[ks][1], aL[ks][2], aL[ks][3], addr + 64);
    }
    __syncthreads();   // Q fragments live in registers; buf1 reusable

    float o[4][4];
#pragma unroll
    for (int nt = 0; nt < 4; nt++)
#pragma unroll
        for (int c = 0; c < 4; c++) o[nt][c] = 0.f;
    float m0 = -1e30f, m1 = -1e30f, l0 = 0.f, l1 = 0.f;

    const int r0 = q0 + wid * 16 + (lane >> 2);
    const int r1 = r0 + 8;
    const int rmax = q0 + wid * 16 + 15;
    const int b_row = lane & 7;
    const int b_k4 = (lane >> 3) * 4;

    for (int t = 0; t < ntiles; t++) {
        if (t + 1 < ntiles) {
            const uint32_t sk = sS + (uint32_t)(((t + 1) & 1) * 4608 * 4);
            const uint32_t* kt = kbase + (size_t)(t + 1) * 64 * 32;
#pragma unroll
            for (int r = 0; r < 2; r++) {
                int idx = tid + r * 256;
                int row = idx >> 3, c4 = idx & 7;
                CP_ASYNC16(sk + (uint32_t)((row * 36 + c4 * 4) * 4), kt + row * 32 + c4 * 4);
            }
            {
                int d = tid >> 3, c4 = tid & 7;
                CP_ASYNC16(sk + (uint32_t)((2304 + d * 36 + c4 * 4) * 4),
                           vhbase + (size_t)d * (TT / 2) + (t + 1) * 32 + c4 * 4);
                CP_ASYNC16(sk + (uint32_t)((3456 + d * 36 + c4 * 4) * 4),
                           vlbase + (size_t)d * (TT / 2) + (t + 1) * 32 + c4 * 4);
            }
            CP_COMMIT();
            CP_WAIT(1);
        } else {
            CP_WAIT(0);
        }
        __syncthreads();

        const int j0 = t * 64;
        if (j0 <= rmax) {
            const uint32_t skb = sS + (uint32_t)((t & 1) * 4608 * 4);

            // ---- scores S = Q K^T (3-term split) ----
            float s[8][4];
#pragma unroll
            for (int tt = 0; tt < 8; tt++)
#pragma unroll
                for (int c = 0; c < 4; c++) s[tt][c] = 0.f;

#pragma unroll
            for (int tt = 0; tt < 8; tt++) {
                uint32_t krow = skb + (uint32_t)(((tt * 8 + b_row) * 36 + b_k4) * 4);
                uint32_t bh0[2], bh1[2], bl0[2], bl1[2];
                LDSM_X4(bh0[0], bh0[1], bh1[0], bh1[1], krow);
                LDSM_X4(bl0[0], bl0[1], bl1[0], bl1[1], krow + 64);
                MMA_16816(s[tt], aH[0], bh0);
                MMA_16816(s[tt], aH[1], bh1);
                MMA_16816(s[tt], aL[0], bh0);
                MMA_16816(s[tt], aL[1], bh1);
                MMA_16816(s[tt], aH[0], bl0);
                MMA_16816(s[tt], aH[1], bl1);
            }

            // ---- masking (boundary tiles only) ----
            const bool needMask = (j0 + 64 > L) || (j0 + 64 > q0 + wid * 16 + 1);
            if (needMask) {
#pragma unroll
                for (int tt = 0; tt < 8; tt++) {
#pragma unroll
                    for (int c = 0; c < 2; c++) {
                        int j = j0 + tt * 8 + (lane & 3) * 2 + c;
                        if (j > r0 || j >= L) s[tt][c] = -1e30f;
                        if (j > r1 || j >= L) s[tt][2 + c] = -1e30f;
                    }
                }
            }

            // ---- online softmax (exp2 domain) ----
            float mt0 = -1e30f, mt1 = -1e30f;
#pragma unroll
            for (int tt = 0; tt < 8; tt++) {
                mt0 = fmaxf(mt0, fmaxf(s[tt][0], s[tt][1]));
                mt1 = fmaxf(mt1, fmaxf(s[tt][2], s[tt][3]));
            }
            mt0 = fmaxf(mt0, __shfl_xor_sync(0xffffffffu, mt0, 1));
            mt0 = fmaxf(mt0, __shfl_xor_sync(0xffffffffu, mt0, 2));
            mt1 = fmaxf(mt1, __shfl_xor_sync(0xffffffffu, mt1, 1));
            mt1 = fmaxf(mt1, __shfl_xor_sync(0xffffffffu, mt1, 2));

            float mn0 = fmaxf(m0, mt0), mn1 = fmaxf(m1, mt1);
            float corr0 = ex2f(m0 - mn0), corr1 = ex2f(m1 - mn1);
            m0 = mn0; m1 = mn1;

            float ps0 = 0.f, ps1 = 0.f;
#pragma unroll
            for (int tt = 0; tt < 8; tt++) {
                s[tt][0] = ex2f(s[tt][0] - mn0);
                s[tt][1] = ex2f(s[tt][1] - mn0);
                s[tt][2] = ex2f(s[tt][2] - mn1);
                s[tt][3] = ex2f(s[tt][3] - mn1);
                ps0 += s[tt][0] + s[tt][1];
                ps1 += s[tt][2] + s[tt][3];
            }
            ps0 += __shfl_xor_sync(0xffffffffu, ps0, 1);
            ps0 += __shfl_xor_sync(0xffffffffu, ps0, 2);
            ps1 += __shfl_xor_sync(0xffffffffu, ps1, 1);
            ps1 += __shfl_xor_sync(0xffffffffu, ps1, 2);
            l0 = l0 * corr0 + ps0;
            l1 = l1 * corr1 + ps1;

#pragma unroll
            for (int nt = 0; nt < 4; nt++) {
                o[nt][0] *= corr0; o[nt][1] *= corr0;
                o[nt][2] *= corr1; o[nt][3] *= corr1;
            }

            // ---- PV: stream P per ks-pair ----
            const uint32_t svhb = skb + 2304 * 4;
            const uint32_t svlb = skb + 3456 * 4;
#pragma unroll
            for (int ksp = 0; ksp < 2; ksp++) {
                uint32_t ph2[2][4], pl2[2][4];
#pragma unroll
                for (int k2 = 0; k2 < 2; k2++) {
                    const int t0 = 4 * ksp + 2 * k2, t1 = t0 + 1;
                    float v[8] = {s[t0][0], s[t0][1], s[t0][2], s[t0][3],
                                  s[t1][0], s[t1][1], s[t1][2], s[t1][3]};
#pragma unroll
                    for (int g = 0; g < 4; g++) {
                        pair_split(v[g * 2], v[g * 2 + 1], ph2[k2][g], pl2[k2][g]);
                    }
                }
#pragma unroll
                for (int nt = 0; nt < 4; nt++) {
                    uint32_t voff = (uint32_t)(((nt * 8 + b_row) * 36 + b_k4) * 4) +
                                    (uint32_t)(ksp * 64);
                    uint32_t bvh[2][2], bvl[2][2];
                    LDSM_X4(bvh[0][0], bvh[0][1], bvh[1][0], bvh[1][1], svhb + voff);
                    LDSM_X4(bvl[0][0], bvl[0][1], bvl[1][0], bvl[1][1], svlb + voff);
#pragma unroll
                    for (int k2 = 0; k2 < 2; k2++) {
                        MMA_16816(o[nt], ph2[k2], bvh[k2]);
                        MMA_16816(o[nt], pl2[k2], bvh[k2]);
                        MMA_16816(o[nt], ph2[k2], bvl[k2]);
                    }
                }
            }
        }
        __syncthreads();
    }

    // ---- epilogue ----
    const float inv0 = 1.f / l0, inv1 = 1.f / l1;
#pragma unroll
    for (int nt = 0; nt < 4; nt++) {
        int d = h * 32 + nt * 8 + (lane & 3) * 2;
        *(float2*)&out[((size_t)(b * TT + r0)) * DD + d] =
            make_float2(o[nt][0] * inv0, o[nt][1] * inv0);
        *(float2*)&out[((size_t)(b * TT + r1)) * DD + d] =
            make_float2(o[nt][2] * inv1, o[nt][3] * inv1);
    }
}

// ---------------------------------------------------------------------------
extern "C" void kernel_launch(void* const* d_in, const int* in_sizes, int n_in,
                              void* d_out, int out_size) {
    const float* x           = (const float*)d_in[0];
    const int*   keys_length = (const int*)d_in[1];
    const float* W           = (const float*)d_in[2];
    const float* W_output    = (const float*)d_in[3];
    const float* gamma       = (const float*)d_in[4];
    const float* beta        = (const float*)d_in[5];
    float* out = (float*)d_out;

    float *qkv_p, *attn_p;
    uint32_t *ws_p, *wos_p, *qsp_p, *ksp_p, *vth_p, *vtl_p;
    cudaGetSymbolAddress((void**)&qkv_p,  g_qkv);
    cudaGetSymbolAddress((void**)&attn_p, g_attn);
    cudaGetSymbolAddress((void**)&ws_p,   g_Ws);
    cudaGetSymbolAddress((void**)&wos_p,  g_WOs);
    cudaGetSymbolAddress((void**)&qsp_p,  g_Qsp);
    cudaGetSymbolAddress((void**)&ksp_p,  g_Ksp);
    cudaGetSymbolAddress((void**)&vth_p,  g_Vth);
    cudaGetSymbolAddress((void**)&vtl_p,  g_Vtl);

    // 0) Weight transpose + split
    wsplit_kernel<<<512, 128>>>(W, W_output, ws_p, wos_p);

    // 1) QKV projection with fused Q/K split epilogue
    gemm_qkv<<<dim3(MROWS / 128, 3), 256>>>(x, ws_p, qsp_p, ksp_p, qkv_p);

    // 2) V transpose-split
    vsplit_kernel<<<dim3(BB * HH, 8), 256>>>(qkv_p, vth_p, vtl_p);

    // 3) Flash attention (HMMA, heavy-first 1D grid)
    attn_hmma<<<1024, 256>>>(qsp_p, keys_length, ksp_p, vth_p, vtl_p, attn_p);

    // 4) Output projection + residual + LayerNorm (fused)
    gemm_out_ln<<<MROWS / 128, 256>>>(attn_p, wos_p, x, gamma, beta, out);
}

// round 8
// speedup vs baseline: 3.3456x; 1.0286x over previous
#include <cuda_runtime.h>
#include <cuda_bf16.h>
#include <cstdint>

// Problem constants
#define BB 32
#define TT 1024
#define DD 128
#define HH 4
#define DHH 32
#define MROWS (BB*TT)   // 32768

// Scratch (device globals — no allocation allowed)
__device__ __align__(16) uint32_t g_Xsp[MROWS * DD];    // x pre-split (u32/elem)
__device__ __align__(16) uint32_t g_Asp[MROWS * DD];    // attn out pre-split
__device__ __align__(16) uint32_t g_Ws[384 * 128];      // W^T split
__device__ __align__(16) uint32_t g_WOs[128 * 128];     // Wout^T split
__device__ __align__(16) uint32_t g_Qsp[MROWS * HH * 32];        // Q split (scaled)
__device__ __align__(16) uint32_t g_Ksp[BB * HH * TT * 32];      // K split rows: 16 hi + 16 lo
__device__ __align__(16) uint32_t g_Vth[BB * HH * 32 * (TT/2)];  // V^T hi: [bh][d][jp]
__device__ __align__(16) uint32_t g_Vtl[BB * HH * 32 * (TT/2)];  // V^T lo

// ---------------------------------------------------------------------------
// helpers
// ---------------------------------------------------------------------------
__device__ __forceinline__ uint32_t smem_u32(const void* p) {
    uint32_t a;
    asm("{ .reg .u64 t; cvta.to.shared.u64 t, %1; cvt.u32.u64 %0, t; }"
        : "=r"(a) : "l"(p));
    return a;
}

__device__ __forceinline__ uint32_t split_pack(float x) {
    __nv_bfloat16 h = __float2bfloat16(x);
    float r = x - __bfloat162float(h);
    __nv_bfloat16 l = __float2bfloat16(r);
    return (uint32_t)__bfloat16_as_ushort(h) | ((uint32_t)__bfloat16_as_ushort(l) << 16);
}

// pack two floats as bf16x2: low 16 = x (even index), high 16 = y (odd index)
__device__ __forceinline__ uint32_t pack_bf16x2(float x, float y) {
    uint32_t d;
    asm("cvt.rn.bf16x2.f32 %0, %1, %2;" : "=r"(d) : "f"(y), "f"(x));
    return d;
}

// pack pair (x,y) into hi bf16x2 + lo bf16x2
__device__ __forceinline__ void pair_split(float x, float y,
                                           uint32_t& hi, uint32_t& lo) {
    hi = pack_bf16x2(x, y);
    float hx = __uint_as_float(hi << 16);
    float hy = __uint_as_float(hi & 0xffff0000u);
    lo = pack_bf16x2(x - hx, y - hy);
}

__device__ __forceinline__ float ex2f(float x) {
    float r;
    asm("ex2.approx.ftz.f32 %0, %1;" : "=f"(r) : "f"(x));
    return r;
}

#define LDSM_X4(r0, r1, r2, r3, addr) \
    asm volatile("ldmatrix.sync.aligned.m8n8.x4.shared.b16 {%0,%1,%2,%3}, [%4];" \
                 : "=r"(r0), "=r"(r1), "=r"(r2), "=r"(r3) : "r"(addr))

#define LDSM_X2(r0, r1, addr) \
    asm volatile("ldmatrix.sync.aligned.m8n8.x2.shared.b16 {%0,%1}, [%2];" \
                 : "=r"(r0), "=r"(r1) : "r"(addr))

#define MMA_16816(c, a, b) \
    asm volatile("mma.sync.aligned.m16n8k16.row.col.f32.bf16.bf16.f32 " \
                 "{%0,%1,%2,%3}, {%4,%5,%6,%7}, {%8,%9}, {%0,%1,%2,%3};" \
                 : "+f"((c)[0]), "+f"((c)[1]), "+f"((c)[2]), "+f"((c)[3]) \
                 : "r"((a)[0]), "r"((a)[1]), "r"((a)[2]), "r"((a)[3]), \
                   "r"((b)[0]), "r"((b)[1]))

#define CP_ASYNC16(dst, src) \
    asm volatile("cp.async.cg.shared.global [%0], [%1], 16;" :: "r"(dst), "l"(src))
#define CP_COMMIT() asm volatile("cp.async.commit_group;" ::: "memory")
#define CP_WAIT(n)  asm volatile("cp.async.wait_group %0;" :: "n"(n) : "memory")

// ---------------------------------------------------------------------------
// Prepass: split x (coalesced) + transpose/split both weight matrices.
// grid 1536: blocks [0,1024) -> x, [1024,1536) -> weights.
// ---------------------------------------------------------------------------
__global__ __launch_bounds__(256) void presplit_kernel(
    const float* __restrict__ x, const float* __restrict__ W,
    const float* __restrict__ Wo, uint32_t* __restrict__ Xsp,
    uint32_t* __restrict__ Ws, uint32_t* __restrict__ WOs) {
    const int bid = blockIdx.x;
    const int tid = threadIdx.x;
    if (bid < 1024) {
#pragma unroll
        for (int r = 0; r < 4; r++) {
            int e = bid * 1024 + r * 256 + tid;   // float4 index
            float4 v = *(const float4*)&x[(size_t)e * 4];
            uint4 o;
            o.x = split_pack(v.x); o.y = split_pack(v.y);
            o.z = split_pack(v.z); o.w = split_pack(v.w);
            *(uint4*)&Xsp[(size_t)e * 4] = o;
        }
    } else {
        int n = bid - 1024;
        if (tid < 128) {
            int k = tid;
            if (n < 384) Ws[n * 128 + k] = split_pack(W[k * 384 + n]);
            else WOs[(n - 384) * 128 + k] = split_pack(Wo[k * 128 + (n - 384)]);
        }
    }
}

// ---------------------------------------------------------------------------
// QKV HMMA GEMM (pre-split A) with fused epilogues:
// y=0: Q scaled+split -> Qsp ; y=1: K split -> Ksp ;
// y=2: V transpose+split -> Vth/Vtl (per-head smem transpose).
// ---------------------------------------------------------------------------
__global__ __launch_bounds__(256) void gemm_qkv(
    const uint32_t* __restrict__ Asp, const uint32_t* __restrict__ Bg,
    uint32_t* __restrict__ Qsp, uint32_t* __restrict__ Ksp,
    uint32_t* __restrict__ Vth, uint32_t* __restrict__ Vtl) {
    __shared__ uint32_t As_s[128 * 36];
    __shared__ uint32_t Bs_s[128 * 36];

    const int tid = threadIdx.x;
    const int wid = tid >> 5;
    const int lane = tid & 31;
    const int wm = wid >> 2;
    const int wn = wid & 3;
    const int m0 = blockIdx.x * 128;
    const int y = blockIdx.y;
    const int n0 = y * 128;

    const uint32_t sa = smem_u32(As_s);
    const uint32_t sb = smem_u32(Bs_s);

    float acc[4][4][4];
#pragma unroll
    for (int i = 0; i < 4; i++)
#pragma unroll
        for (int j = 0; j < 4; j++)
#pragma unroll
            for (int q = 0; q < 4; q++) acc[i][j][q] = 0.f;

    const int a_row = lane & 15;
    const int a_koff = (lane >> 4) * 4;
    const int b_row = lane & 7;
    const int b_koff = ((lane >> 3) & 1) * 4;

    for (int ch = 0; ch < 4; ch++) {
        const int kc = ch * 32;
#pragma unroll
        for (int r = 0; r < 4; r++) {
            int idx = tid + r * 256;
            int row = idx >> 3, c4 = idx & 7;
            uint4 v = *(const uint4*)&Asp[(size_t)(m0 + row) * 128 + kc + c4 * 4];
            uint32_t* d = &As_s[row * 36 + c4 * 4];
            d[0] = v.x; d[1] = v.y; d[2] = v.z; d[3] = v.w;
        }
#pragma unroll
        for (int r = 0; r < 4; r++) {
            int idx = tid + r * 256;
            int row = idx >> 3, c16 = idx & 7;
            uint4 v = *(const uint4*)&Bg[(size_t)(n0 + row) * 128 + kc + c16 * 4];
            uint32_t* d = &Bs_s[row * 36 + c16 * 4];
            d[0] = v.x; d[1] = v.y; d[2] = v.z; d[3] = v.w;
        }
        __syncthreads();

#pragma unroll
        for (int s = 0; s < 4; s++) {
            uint32_t af[4][4];
#pragma unroll
            for (int tm = 0; tm < 4; tm++) {
                uint32_t addr = sa + (uint32_t)(((wm * 64 + tm * 16 + a_row) * 36 +
                                                 s * 8 + a_koff) * 4);
                LDSM_X4(af[tm][0], af[tm][1], af[tm][2], af[tm][3], addr);
            }
            uint32_t bf[4][2];
#pragma unroll
            for (int tn = 0; tn < 4; tn++) {
                uint32_t addr = sb + (uint32_t)(((wn * 32 + tn * 8 + b_row) * 36 +
                                                 s * 8 + b_koff) * 4);
                LDSM_X2(bf[tn][0], bf[tn][1], addr);
            }
#pragma unroll
            for (int tm = 0; tm < 4; tm++)
#pragma unroll
                for (int tn = 0; tn < 4; tn++)
                    MMA_16816(acc[tm][tn], af[tm], bf[tn]);
        }
        __syncthreads();
    }

    const int er = lane >> 2;
    const int ec = (lane & 3) * 2;
    const float qscale = 0.17677669529663687f * 1.4426950408889634f;

    if (y == 2) {
        // V: per-head smem transpose + split -> Vth/Vtl
        float* sv = (float*)As_s;   // [128][34] floats = 17.4 KB (fits in As_s)
        const int b = m0 >> 10;
        const int jb0 = m0 & 1023;
#pragma unroll
        for (int h = 0; h < 4; h++) {
            if (h) __syncthreads();     // guard store-after-read of sv
            if (wn == h) {
#pragma unroll
                for (int tm = 0; tm < 4; tm++) {
#pragma unroll
                    for (int tn = 0; tn < 4; tn++) {
                        int rl = wm * 64 + tm * 16 + er;
                        int cl = tn * 8 + ec;
                        *(float2*)&sv[rl * 34 + cl] =
                            make_float2(acc[tm][tn][0], acc[tm][tn][1]);
                        *(float2*)&sv[(rl + 8) * 34 + cl] =
                            make_float2(acc[tm][tn][2], acc[tm][tn][3]);
                    }
                }
            }
            __syncthreads();
            const int bh = b * 4 + h;
#pragma unroll
            for (int r = 0; r < 8; r++) {
                int idx = tid + r * 256;    // 0..2047
                int d = idx >> 6, jp = idx & 63;
                uint32_t hi, lo;
                pair_split(sv[(jp * 2) * 34 + d], sv[(jp * 2 + 1) * 34 + d], hi, lo);
                size_t o = (size_t)(bh * 32 + d) * (TT / 2) + (jb0 >> 1) + jp;
                Vth[o] = hi;
                Vtl[o] = lo;
            }
        }
    } else {
        const float sc = (y == 0) ? qscale : 1.f;
#pragma unroll
        for (int tm = 0; tm < 4; tm++) {
#pragma unroll
            for (int tn = 0; tn < 4; tn++) {
                int row = m0 + wm * 64 + tm * 16 + er;
                int col = wn * 32 + tn * 8 + ec;
                int head = col >> 5;
                int dp = (col & 31) >> 1;
                uint32_t hi0, lo0, hi1, lo1;
                pair_split(acc[tm][tn][0] * sc, acc[tm][tn][1] * sc, hi0, lo0);
                pair_split(acc[tm][tn][2] * sc, acc[tm][tn][3] * sc, hi1, lo1);
                if (y == 0) {
                    uint32_t* d0 = &Qsp[((size_t)row * 4 + head) * 32];
                    uint32_t* d1 = &Qsp[((size_t)(row + 8) * 4 + head) * 32];
                    d0[dp] = hi0; d0[16 + dp] = lo0;
                    d1[dp] = hi1; d1[16 + dp] = lo1;
                } else {
                    int bb = row >> 10;
                    int t0 = row & 1023;
                    uint32_t* d0 = &Ksp[(((size_t)bb * 4 + head) * 1024 + t0) * 32];
                    uint32_t* d1 = d0 + 8 * 32;
                    d0[dp] = hi0; d0[16 + dp] = lo0;
                    d1[dp] = hi1; d1[16 + dp] = lo1;
                }
            }
        }
    }
}

// ---------------------------------------------------------------------------
// Fused output projection (pre-split A) + residual + LayerNorm.
// ---------------------------------------------------------------------------
__global__ __launch_bounds__(256) void gemm_out_ln(
    const uint32_t* __restrict__ Asp, const uint32_t* __restrict__ Bg,
    const float* __restrict__ x, const float* __restrict__ gamma,
    const float* __restrict__ beta, float* __restrict__ out) {
    __shared__ uint32_t As_s[128 * 36];
    __shared__ uint32_t Bs_s[128 * 36];

    const int tid = threadIdx.x;
    const int wid = tid >> 5;
    const int lane = tid & 31;
    const int wm = wid >> 2;
    const int wn = wid & 3;
    const int m0 = blockIdx.x * 128;

    const uint32_t sa = smem_u32(As_s);
    const uint32_t sb = smem_u32(Bs_s);

    float acc[4][4][4];
#pragma unroll
    for (int i = 0; i < 4; i++)
#pragma unroll
        for (int j = 0; j < 4; j++)
#pragma unroll
            for (int q = 0; q < 4; q++) acc[i][j][q] = 0.f;

    const int a_row = lane & 15;
    const int a_koff = (lane >> 4) * 4;
    const int b_row = lane & 7;
    const int b_koff = ((lane >> 3) & 1) * 4;

    for (int ch = 0; ch < 4; ch++) {
        const int kc = ch * 32;
#pragma unroll
        for (int r = 0; r < 4; r++) {
            int idx = tid + r * 256;
            int row = idx >> 3, c4 = idx & 7;
            uint4 v = *(const uint4*)&Asp[(size_t)(m0 + row) * 128 + kc + c4 * 4];
            uint32_t* d = &As_s[row * 36 + c4 * 4];
            d[0] = v.x; d[1] = v.y; d[2] = v.z; d[3] = v.w;
        }
#pragma unroll
        for (int r = 0; r < 4; r++) {
            int idx = tid + r * 256;
            int row = idx >> 3, c16 = idx & 7;
            uint4 v = *(const uint4*)&Bg[(size_t)row * 128 + kc + c16 * 4];
            uint32_t* d = &Bs_s[row * 36 + c16 * 4];
            d[0] = v.x; d[1] = v.y; d[2] = v.z; d[3] = v.w;
        }
        __syncthreads();

#pragma unroll
        for (int s = 0; s < 4; s++) {
            uint32_t af[4][4];
#pragma unroll
            for (int tm = 0; tm < 4; tm++) {
                uint32_t addr = sa + (uint32_t)(((wm * 64 + tm * 16 + a_row) * 36 +
                                                 s * 8 + a_koff) * 4);
                LDSM_X4(af[tm][0], af[tm][1], af[tm][2], af[tm][3], addr);
            }
            uint32_t bf[4][2];
#pragma unroll
            for (int tn = 0; tn < 4; tn++) {
                uint32_t addr = sb + (uint32_t)(((wn * 32 + tn * 8 + b_row) * 36 +
                                                 s * 8 + b_koff) * 4);
                LDSM_X2(bf[tn][0], bf[tn][1], addr);
            }
#pragma unroll
            for (int tm = 0; tm < 4; tm++)
#pragma unroll
                for (int tn = 0; tn < 4; tn++)
                    MMA_16816(acc[tm][tn], af[tm], bf[tn]);
        }
        __syncthreads();
    }

    // ---- epilogue: residual + LN ----
    const int er = lane >> 2;
    const int ec = (lane & 3) * 2;

#pragma unroll
    for (int tm = 0; tm < 4; tm++) {
#pragma unroll
        for (int tn = 0; tn < 4; tn++) {
            int row = m0 + wm * 64 + tm * 16 + er;
            int col = wn * 32 + tn * 8 + ec;
            float2 x0 = *(const float2*)&x[(size_t)row * 128 + col];
            float2 x1 = *(const float2*)&x[(size_t)(row + 8) * 128 + col];
            acc[tm][tn][0] += x0.x; acc[tm][tn][1] += x0.y;
            acc[tm][tn][2] += x1.x; acc[tm][tn][3] += x1.y;
        }
    }

    float2* red = (float2*)As_s;
#pragma unroll
    for (int tm = 0; tm < 4; tm++) {
        float s0 = 0.f, q0 = 0.f, s1 = 0.f, q1 = 0.f;
#pragma unroll
        for (int tn = 0; tn < 4; tn++) {
            s0 += acc[tm][tn][0] + acc[tm][tn][1];
            q0 += acc[tm][tn][0] * acc[tm][tn][0] + acc[tm][tn][1] * acc[tm][tn][1];
            s1 += acc[tm][tn][2] + acc[tm][tn][3];
            q1 += acc[tm][tn][2] * acc[tm][tn][2] + acc[tm][tn][3] * acc[tm][tn][3];
        }
#pragma unroll
        for (int off = 1; off < 4; off <<= 1) {
            s0 += __shfl_xor_sync(0xffffffffu, s0, off);
            q0 += __shfl_xor_sync(0xffffffffu, q0, off);
            s1 += __shfl_xor_sync(0xffffffffu, s1, off);
            q1 += __shfl_xor_sync(0xffffffffu, q1, off);
        }
        if ((lane & 3) == 0) {
            int rl = wm * 64 + tm * 16 + er;
            red[wn * 128 + rl] = make_float2(s0, q0);
            red[wn * 128 + rl + 8] = make_float2(s1, q1);
        }
    }
    __syncthreads();

    float2 gm[4], bt[4];
#pragma unroll
    for (int tn = 0; tn < 4; tn++) {
        int col = wn * 32 + tn * 8 + ec;
        gm[tn] = *(const float2*)&gamma[col];
        bt[tn] = *(const float2*)&beta[col];
    }

#pragma unroll
    for (int tm = 0; tm < 4; tm++) {
        int rl = wm * 64 + tm * 16 + er;
        float s0 = 0.f, q0 = 0.f, s1 = 0.f, q1 = 0.f;
#pragma unroll
        for (int w = 0; w < 4; w++) {
            float2 p0 = red[w * 128 + rl];
            float2 p1 = red[w * 128 + rl + 8];
            s0 += p0.x; q0 += p0.y;
            s1 += p1.x; q1 += p1.y;
        }
        float mean0 = s0 * (1.f / 128.f);
        float var0 = q0 * (1.f / 128.f) - mean0 * mean0;
        float rstd0 = rsqrtf(var0 + 1e-9f);
        float mean1 = s1 * (1.f / 128.f);
        float var1 = q1 * (1.f / 128.f) - mean1 * mean1;
        float rstd1 = rsqrtf(var1 + 1e-9f);

        int row = m0 + rl;
#pragma unroll
        for (int tn = 0; tn < 4; tn++) {
            int col = wn * 32 + tn * 8 + ec;
            float2 o0 = make_float2(
                (acc[tm][tn][0] - mean0) * rstd0 * gm[tn].x + bt[tn].x,
                (acc[tm][tn][1] - mean0) * rstd0 * gm[tn].y + bt[tn].y);
            float2 o1 = make_float2(
                (acc[tm][tn][2] - mean1) * rstd1 * gm[tn].x + bt[tn].x,
                (acc[tm][tn][3] - mean1) * rstd1 * gm[tn].y + bt[tn].y);
            *(float2*)&out[(size_t)row * 128 + col] = o0;
            *(float2*)&out[(size_t)(row + 8) * 128 + col] = o1;
        }
    }
}

// ---------------------------------------------------------------------------
// HMMA flash attention: pre-split Q/K/V, cp.async double-buffering, X4 loads,
// globally heavy-first 1D grid. Output written PRE-SPLIT (u32/elem).
// ---------------------------------------------------------------------------
__global__ __launch_bounds__(256, 3) void attn_hmma(
    const uint32_t* __restrict__ Qsp, const int* __restrict__ keys_length,
    const uint32_t* __restrict__ Ksp, const uint32_t* __restrict__ Vth,
    const uint32_t* __restrict__ Vtl, uint32_t* __restrict__ outsp) {
    __shared__ __align__(16) uint32_t S[9216];

    const int bid = blockIdx.x;
    const int q0 = (7 - (bid >> 7)) * 128;
    const int bh = bid & 127;
    const int h = bh & 3;
    const int b = bh >> 2;
    const int tid = threadIdx.x;
    const int wid = tid >> 5;
    const int lane = tid & 31;
    const uint32_t sS = smem_u32(S);

    const int L = keys_length[b];
    const int kend = min(q0 + 128, L);
    const int ntiles = (kend + 63) >> 6;

    const uint32_t* kbase = Ksp + (size_t)(bh * TT) * 32;
    const uint32_t* vhbase = Vth + (size_t)(bh * 32) * (TT / 2);
    const uint32_t* vlbase = Vtl + (size_t)(bh * 32) * (TT / 2);

    // ---- prefetch tile 0 (buf0) + pre-split Q (buf1) ----
    {
        const uint32_t sk = sS;
        const uint32_t* kt = kbase;
#pragma unroll
        for (int r = 0; r < 2; r++) {
            int idx = tid + r * 256;
            int row = idx >> 3, c4 = idx & 7;
            CP_ASYNC16(sk + (uint32_t)((row * 36 + c4 * 4) * 4), kt + row * 32 + c4 * 4);
        }
        {
            int d = tid >> 3, c4 = tid & 7;
            CP_ASYNC16(sk + (uint32_t)((2304 + d * 36 + c4 * 4) * 4),
                       vhbase + (size_t)d * (TT / 2) + c4 * 4);
            CP_ASYNC16(sk + (uint32_t)((3456 + d * 36 + c4 * 4) * 4),
                       vlbase + (size_t)d * (TT / 2) + c4 * 4);
        }
#pragma unroll
        for (int r = 0; r < 4; r++) {
            int idx = tid + r * 256;
            int row = idx >> 3, c4 = idx & 7;
            CP_ASYNC16(sS + (uint32_t)((4608 + row * 36 + c4 * 4) * 4),
                       Qsp + ((size_t)(b * TT + q0 + row) * 4 + h) * 32 + c4 * 4);
        }
        CP_COMMIT();
    }

    CP_WAIT(0);
    __syncthreads();

    const int a_row = lane & 15;
    const int a_koff = (lane >> 4) * 4;
    uint32_t aH[2][4], aL[2][4];
#pragma unroll
    for (int ks = 0; ks < 2; ks++) {
        uint32_t addr = sS + (uint32_t)((4608 + (wid * 16 + a_row) * 36 + ks * 8 + a_koff) * 4);
        LDSM_X4(aH[ks][0], aH[ks][1], aH[ks][2], aH[ks][3], addr);
        LDSM_X4(aL[ks][0], aL[ks][1], aL[ks][2], aL[ks][3], addr + 64);
    }
    __syncthreads();

    float o[4][4];
#pragma unroll
    for (int nt = 0; nt < 4; nt++)
#pragma unroll
        for (int c = 0; c < 4; c++) o[nt][c] = 0.f;
    float m0 = -1e30f, m1 = -1e30f, l0 = 0.f, l1 = 0.f;

    const int r0 = q0 + wid * 16 + (lane >> 2);
    const int r1 = r0 + 8;
    const int rmax = q0 + wid * 16 + 15;
    const int b_row = lane & 7;
    const int b_k4 = (lane >> 3) * 4;

    for (int t = 0; t < ntiles; t++) {
        if (t + 1 < ntiles) {
            const uint32_t sk = sS + (uint32_t)(((t + 1) & 1) * 4608 * 4);
            const uint32_t* kt = kbase + (size_t)(t + 1) * 64 * 32;
#pragma unroll
            for (int r = 0; r < 2; r++) {
                int idx = tid + r * 256;
                int row = idx >> 3, c4 = idx & 7;
                CP_ASYNC16(sk + (uint32_t)((row * 36 + c4 * 4) * 4), kt + row * 32 + c4 * 4);
            }
            {
                int d = tid >> 3, c4 = tid & 7;
                CP_ASYNC16(sk + (uint32_t)((2304 + d * 36 + c4 * 4) * 4),
                           vhbase + (size_t)d * (TT / 2) + (t + 1) * 32 + c4 * 4);
                CP_ASYNC16(sk + (uint32_t)((3456 + d * 36 + c4 * 4) * 4),
                           vlbase + (size_t)d * (TT / 2) + (t + 1) * 32 + c4 * 4);
            }
            CP_COMMIT();
            CP_WAIT(1);
        } else {
            CP_WAIT(0);
        }
        __syncthreads();

        const int j0 = t * 64;
        if (j0 <= rmax) {
            const uint32_t skb = sS + (uint32_t)((t & 1) * 4608 * 4);

            float s[8][4];
#pragma unroll
            for (int tt = 0; tt < 8; tt++)
#pragma unroll
                for (int c = 0; c < 4; c++) s[tt][c] = 0.f;

#pragma unroll
            for (int tt = 0; tt < 8; tt++) {
                uint32_t krow = skb + (uint32_t)(((tt * 8 + b_row) * 36 + b_k4) * 4);
                uint32_t bh0[2], bh1[2], bl0[2], bl1[2];
                LDSM_X4(bh0[0], bh0[1], bh1[0], bh1[1], krow);
                LDSM_X4(bl0[0], bl0[1], bl1[0], bl1[1], krow + 64);
                MMA_16816(s[tt], aH[0], bh0);
                MMA_16816(s[tt], aH[1], bh1);
                MMA_16816(s[tt], aL[0], bh0);
                MMA_16816(s[tt], aL[1], bh1);
                MMA_16816(s[tt], aH[0], bl0);
                MMA_16816(s[tt], aH[1], bl1);
            }

            const bool needMask = (j0 + 64 > L) || (j0 + 64 > q0 + wid * 16 + 1);
            if (needMask) {
#pragma unroll
                for (int tt = 0; tt < 8; tt++) {
#pragma unroll
                    for (int c = 0; c < 2; c++) {
                        int j = j0 + tt * 8 + (lane & 3) * 2 + c;
                        if (j > r0 || j >= L) s[tt][c] = -1e30f;
                        if (j > r1 || j >= L) s[tt][2 + c] = -1e30f;
                    }
                }
            }

            float mt0 = -1e30f, mt1 = -1e30f;
#pragma unroll
            for (int tt = 0; tt < 8; tt++) {
                mt0 = fmaxf(mt0, fmaxf(s[tt][0], s[tt][1]));
                mt1 = fmaxf(mt1, fmaxf(s[tt][2], s[tt][3]));
            }
            mt0 = fmaxf(mt0, __shfl_xor_sync(0xffffffffu, mt0, 1));
            mt0 = fmaxf(mt0, __shfl_xor_sync(0xffffffffu, mt0, 2));
            mt1 = fmaxf(mt1, __shfl_xor_sync(0xffffffffu, mt1, 1));
            mt1 = fmaxf(mt1, __shfl_xor_sync(0xffffffffu, mt1, 2));

            float mn0 = fmaxf(m0, mt0), mn1 = fmaxf(m1, mt1);
            float corr0 = ex2f(m0 - mn0), corr1 = ex2f(m1 - mn1);
            m0 = mn0; m1 = mn1;

            float ps0 = 0.f, ps1 = 0.f;
#pragma unroll
            for (int tt = 0; tt < 8; tt++) {
                s[tt][0] = ex2f(s[tt][0] - mn0);
                s[tt][1] = ex2f(s[tt][1] - mn0);
                s[tt][2] = ex2f(s[tt][2] - mn1);
                s[tt][3] = ex2f(s[tt][3] - mn1);
                ps0 += s[tt][0] + s[tt][1];
                ps1 += s[tt][2] + s[tt][3];
            }
            ps0 += __shfl_xor_sync(0xffffffffu, ps0, 1);
            ps0 += __shfl_xor_sync(0xffffffffu, ps0, 2);
            ps1 += __shfl_xor_sync(0xffffffffu, ps1, 1);
            ps1 += __shfl_xor_sync(0xffffffffu, ps1, 2);
            l0 = l0 * corr0 + ps0;
            l1 = l1 * corr1 + ps1;

#pragma unroll
            for (int nt = 0; nt < 4; nt++) {
                o[nt][0] *= corr0; o[nt][1] *= corr0;
                o[nt][2] *= corr1; o[nt][3] *= corr1;
            }

            const uint32_t svhb = skb + 2304 * 4;
            const uint32_t svlb = skb + 3456 * 4;
#pragma unroll
            for (int ksp = 0; ksp < 2; ksp++) {
                uint32_t ph2[2][4], pl2[2][4];
#pragma unroll
                for (int k2 = 0; k2 < 2; k2++) {
                    const int t0 = 4 * ksp + 2 * k2, t1 = t0 + 1;
                    float v[8] = {s[t0][0], s[t0][1], s[t0][2], s[t0][3],
                                  s[t1][0], s[t1][1], s[t1][2], s[t1][3]};
#pragma unroll
                    for (int g = 0; g < 4; g++) {
                        pair_split(v[g * 2], v[g * 2 + 1], ph2[k2][g], pl2[k2][g]);
                    }
                }
#pragma unroll
                for (int nt = 0; nt < 4; nt++) {
                    uint32_t voff = (uint32_t)(((nt * 8 + b_row) * 36 + b_k4) * 4) +
                                    (uint32_t)(ksp * 64);
                    uint32_t bvh[2][2], bvl[2][2];
                    LDSM_X4(bvh[0][0], bvh[0][1], bvh[1][0], bvh[1][1], svhb + voff);
                    LDSM_X4(bvl[0][0], bvl[0][1], bvl[1][0], bvl[1][1], svlb + voff);
#pragma unroll
                    for (int k2 = 0; k2 < 2; k2++) {
                        MMA_16816(o[nt], ph2[k2], bvh[k2]);
                        MMA_16816(o[nt], pl2[k2], bvh[k2]);
                        MMA_16816(o[nt], ph2[k2], bvl[k2]);
                    }
                }
            }
        }
        __syncthreads();
    }

    // ---- epilogue: write pre-split output (u32 per element) ----
    const float inv0 = 1.f / l0, inv1 = 1.f / l1;
#pragma unroll
    for (int nt = 0; nt < 4; nt++) {
        int d = h * 32 + nt * 8 + (lane & 3) * 2;
        *(uint2*)&outsp[((size_t)(b * TT + r0)) * DD + d] =
            make_uint2(split_pack(o[nt][0] * inv0), split_pack(o[nt][1] * inv0));
        *(uint2*)&outsp[((size_t)(b * TT + r1)) * DD + d] =
            make_uint2(split_pack(o[nt][2] * inv1), split_pack(o[nt][3] * inv1));
    }
}

// ---------------------------------------------------------------------------
extern "C" void kernel_launch(void* const* d_in, const int* in_sizes, int n_in,
                              void* d_out, int out_size) {
    const float* x           = (const float*)d_in[0];
    const int*   keys_length = (const int*)d_in[1];
    const float* W           = (const float*)d_in[2];
    const float* W_output    = (const float*)d_in[3];
    const float* gamma       = (const float*)d_in[4];
    const float* beta        = (const float*)d_in[5];
    float* out = (float*)d_out;

    uint32_t *xsp_p, *asp_p, *ws_p, *wos_p, *qsp_p, *ksp_p, *vth_p, *vtl_p;
    cudaGetSymbolAddress((void**)&xsp_p, g_Xsp);
    cudaGetSymbolAddress((void**)&asp_p, g_Asp);
    cudaGetSymbolAddress((void**)&ws_p,  g_Ws);
    cudaGetSymbolAddress((void**)&wos_p, g_WOs);
    cudaGetSymbolAddress((void**)&qsp_p, g_Qsp);
    cudaGetSymbolAddress((void**)&ksp_p, g_Ksp);
    cudaGetSymbolAddress((void**)&vth_p, g_Vth);
    cudaGetSymbolAddress((void**)&vtl_p, g_Vtl);

    // 0) Split x + both weight matrices (one node)
    presplit_kernel<<<1536, 256>>>(x, W, W_output, xsp_p, ws_p, wos_p);

    // 1) QKV projection; epilogues emit Qsp/Ksp/Vth/Vtl directly
    gemm_qkv<<<dim3(MROWS / 128, 3), 256>>>(xsp_p, ws_p, qsp_p, ksp_p,
                                            vth_p, vtl_p);

    // 2) Flash attention (HMMA); output pre-split
    attn_hmma<<<1024, 256>>>(qsp_p, keys_length, ksp_p, vth_p, vtl_p, asp_p);

    // 3) Output projection + residual + LayerNorm (fused)
    gemm_out_ln<<<MROWS / 128, 256>>>(asp_p, wos_p, x, gamma, beta, out);
}